// round 11
// baseline (speedup 1.0000x reference)
#include <cuda_runtime.h>
#include <cuda_fp16.h>
#include <cstdint>

#define B_SZ 32768
#define DIN_SZ 784
#define D_SZ 256
#define T_SZ 16
#define C_SZ 64
#define NCHUNK 13            // K padded to 832, BK=64
#define NBLK (B_SZ / 128)

// ---------------- scratch (static __device__, no allocs) ----------------
__device__ uint32_t g_h16[2][B_SZ][128];     // h hi/lo fp16 pairs (x16 scaled)
__device__ int   g_rowlist[T_SZ * B_SZ];
__device__ int   g_counts[T_SZ];
__device__ uint4 g_B16[2][NCHUNK][2048];     // Wp^T hi/lo fp16 swizzled
__device__ uint4 g_Ws16[2][NCHUNK][128];     // Ws^T hi/lo fp16 swizzled
__device__ uint4 g_Wc16[2][T_SZ][4][512];    // Wc^T hi/lo fp16 swizzled per tile/chunk
__device__ float g_bs[T_SZ];                 // 1024 * (bp @ q(sigs)^T)

#define XSCALE 16.0f
#define WSCALE 64.0f
#define INVSCALE (1.0f / 1024.0f)

// ---------------- helpers ----------------
__device__ __forceinline__ uint32_t smem_u32(const void* p) {
    uint32_t a;
    asm("{ .reg .u64 t; cvta.to.shared.u64 t, %1; cvt.u32.u64 %0, t; }" : "=r"(a) : "l"(p));
    return a;
}
#define SWZ128(o) ((o) ^ (((o) >> 3) & 0x70))

#define CP_ASYNC16(dst, src) \
    asm volatile("cp.async.cg.shared.global [%0], [%1], 16;" :: "r"(dst), "l"(src))
#define CP_COMMIT() asm volatile("cp.async.commit_group;" ::: "memory")
#define CP_WAIT(n)  asm volatile("cp.async.wait_group %0;" :: "n"(n) : "memory")

__device__ __forceinline__ void ldsm4(uint32_t* r, uint32_t addr) {
    asm volatile("ldmatrix.sync.aligned.m8n8.x4.shared.b16 {%0,%1,%2,%3}, [%4];"
                 : "=r"(r[0]), "=r"(r[1]), "=r"(r[2]), "=r"(r[3]) : "r"(addr));
}
__device__ __forceinline__ void mma16816(float* c, const uint32_t* a, const uint32_t* b) {
    asm volatile("mma.sync.aligned.m16n8k16.row.col.f32.f16.f16.f32 "
                 "{%0,%1,%2,%3}, {%4,%5,%6,%7}, {%8,%9}, {%0,%1,%2,%3};"
                 : "+f"(c[0]), "+f"(c[1]), "+f"(c[2]), "+f"(c[3])
                 : "r"(a[0]), "r"(a[1]), "r"(a[2]), "r"(a[3]), "r"(b[0]), "r"(b[1]));
}
__device__ __forceinline__ uint32_t pack_h2(float a, float b) {
    __half h0 = __float2half_rn(a), h1 = __float2half_rn(b);
    return ((uint32_t)__half_as_ushort(h1) << 16) | __half_as_ushort(h0);
}

// ========================================================================
// Fused prep kernel: blockIdx [0,26) = prep_B halves; [26,90) = prep_Wc;
// [90,142) = prep_Ws (16 k rows per block). One launch.
// ========================================================================
__device__ void prep_B_body(int blk, const float* __restrict__ Wp, char* s_all) {
    float (*ws_s)[256] = (float(*)[256])s_all;
    const int ci   = blk >> 1;
    const int half = blk & 1;
    const int tid  = threadIdx.x;
    const int kbase = ci * 64 + half * 32;

    for (int e = tid; e < 2048; e += 256) {
        const int r = e >> 6, c4 = e & 63;
        const int k = kbase + r;
        float4 v = make_float4(0.f, 0.f, 0.f, 0.f);
        if (k < DIN_SZ) v = ((const float4*)(Wp + (size_t)k * D_SZ))[c4];
        *(float4*)&ws_s[r][c4 * 4] = v;
    }
    __syncthreads();

    #pragma unroll
    for (int i = 0; i < 4; i++) {
        const int e  = tid + i * 256;
        const int n  = e & 255;
        const int kq = e >> 8;
        float v[8], h[8];
        #pragma unroll
        for (int j = 0; j < 8; j++) {
            v[j] = ws_s[kq * 8 + j][n] * WSCALE;
            h[j] = __half2float(__float2half_rn(v[j]));
        }
        uint4 hi, lo;
        hi.x = pack_h2(v[0], v[1]); hi.y = pack_h2(v[2], v[3]);
        hi.z = pack_h2(v[4], v[5]); hi.w = pack_h2(v[6], v[7]);
        lo.x = pack_h2(v[0] - h[0], v[1] - h[1]); lo.y = pack_h2(v[2] - h[2], v[3] - h[3]);
        lo.z = pack_h2(v[4] - h[4], v[5] - h[5]); lo.w = pack_h2(v[6] - h[6], v[7] - h[7]);
        const uint32_t off = SWZ128((uint32_t)(n * 128 + (half * 4 + kq) * 16));
        g_B16[0][ci][off >> 4] = hi;
        g_B16[1][ci][off >> 4] = lo;
    }
}

__device__ void prep_Wc_body(int blk, const float* __restrict__ Wc, char* s_all) {
    float (*wc_s)[64] = (float(*)[64])s_all;
    const int t   = blk >> 2;
    const int ci  = blk & 3;
    const int tid = threadIdx.x;

    #pragma unroll
    for (int i = 0; i < 4; i++) {
        const int e = tid + i * 256;
        const int r = e >> 4, c4 = e & 15;
        *(float4*)&wc_s[r][c4 * 4] =
            ((const float4*)(Wc + ((size_t)t * 256 + ci * 64 + r) * C_SZ))[c4];
    }
    __syncthreads();

    #pragma unroll
    for (int i = 0; i < 2; i++) {
        const int e = tid + i * 256;
        const int n = e >> 3, q = e & 7;
        float v[8], h[8];
        #pragma unroll
        for (int j = 0; j < 8; j++) {
            v[j] = wc_s[q * 8 + j][n] * WSCALE;
            h[j] = __half2float(__float2half_rn(v[j]));
        }
        uint4 hi, lo;
        hi.x = pack_h2(v[0], v[1]); hi.y = pack_h2(v[2], v[3]);
        hi.z = pack_h2(v[4], v[5]); hi.w = pack_h2(v[6], v[7]);
        lo.x = pack_h2(v[0] - h[0], v[1] - h[1]); lo.y = pack_h2(v[2] - h[2], v[3] - h[3]);
        lo.z = pack_h2(v[4] - h[4], v[5] - h[5]); lo.w = pack_h2(v[6] - h[6], v[7] - h[7]);
        const uint32_t off = SWZ128((uint32_t)(n * 128 + q * 16));
        g_Wc16[0][t][ci][off >> 4] = hi;
        g_Wc16[1][t][ci][off >> 4] = lo;
    }
}

__device__ void prep_Ws_body(int blk, const float* __restrict__ Wp,
                             const float* __restrict__ bp,
                             const float* __restrict__ sigs_raw, char* s_all) {
    float (*q_s)[257] = (float(*)[257])s_all;                    // [16][257]
    float (*w_s)[257] = (float(*)[257])(s_all + 16 * 257 * 4);   // [16][257]
    const int tid = threadIdx.x;
    const int k0  = blk * 16;

    if (blk == 0 && tid < T_SZ) g_counts[tid] = 0;

    for (int e = tid; e < T_SZ * D_SZ; e += 256) {
        const int t = e >> 8, d = e & 255;
        float s = sigs_raw[e];
        q_s[t][d] = (s > 0.3f) ? 1.0f : ((s < -0.3f) ? -1.0f : 0.0f);
    }
    for (int e = tid; e < 16 * D_SZ; e += 256) {
        const int r = e >> 8, d = e & 255;
        const int k = k0 + r;
        w_s[r][d] = (k < DIN_SZ) ? Wp[(size_t)k * D_SZ + d] : 0.f;
    }
    __syncthreads();

    const int ty = tid >> 4;       // 0..15
    const int t  = tid & 15;
    const int k  = k0 + ty;
    float acc = 0.f;
    #pragma unroll 8
    for (int d = 0; d < D_SZ; d++) acc += w_s[ty][d] * q_s[t][d];

    acc *= WSCALE;
    __half hi = __float2half_rn(acc);
    __half lo = __float2half_rn(acc - __half2float(hi));
    const int ci = k >> 6, kin = k & 63;
    const uint32_t off = SWZ128((uint32_t)(t * 128 + kin * 2));
    *(unsigned short*)((char*)g_Ws16[0][ci] + off) = __half_as_ushort(hi);
    *(unsigned short*)((char*)g_Ws16[1][ci] + off) = __half_as_ushort(lo);

    if (blk == 0 && tid < T_SZ) {
        float a = 0.f;
        for (int d = 0; d < D_SZ; d++) a += bp[d] * q_s[tid][d];
        g_bs[tid] = a * (XSCALE * WSCALE);
    }
}

__global__ __launch_bounds__(256)
void prep_all_kernel(const float* __restrict__ Wp,
                     const float* __restrict__ bp,
                     const float* __restrict__ sigs_raw,
                     const float* __restrict__ Wc) {
    __shared__ __align__(16) char s_all[33024];
    const int b = blockIdx.x;
    if (b < 26)       prep_B_body(b, Wp, s_all);
    else if (b < 90)  prep_Wc_body(b - 26, Wc, s_all);
    else              prep_Ws_body(b - 90, Wp, bp, sigs_raw, s_all);
}

// ========================================================================
// Kernel 1: 512 threads / 16 warps (4M x 4N), warp tile 32x64, BK=64.
// Single-product h GEMM; 3-product score strip distributed over ALL 16
// warps (warp w: rows (w&7)*16, n-half w>>3) for balanced barrier arrival.
// ========================================================================
#define NT1 512
#define SMEM1 139264
#define A_ST(st, sp) ((st) * 32768 + (sp) * 16384)
#define B_ST(st)     (65536 + (st) * 32768)
#define W_ST(st, sp) (131072 + (st) * 4096 + (sp) * 2048)

__global__ __launch_bounds__(NT1, 1)
void k1_proj_route(const float* __restrict__ x,
                   const float* __restrict__ bp,
                   float* __restrict__ out_idx,
                   int write_idx)
{
    extern __shared__ char sm[];
    __shared__ float bp_s[D_SZ];
    __shared__ float sb_s[T_SZ];
    __shared__ float s_bv[128];
    __shared__ int   s_bi[128];
    __shared__ int s_cnt[T_SZ];
    __shared__ int s_base[T_SZ];

    const int tid  = threadIdx.x;
    const int lane = tid & 31;
    const int wid  = tid >> 5;
    const int wm   = wid >> 2;          // 0..3 (32-row groups)
    const int wn   = wid & 3;           // 0..3 (64-col groups)
    const int nh   = wid >> 3;          // strip n-half (0: cols 0-7, 1: cols 8-15)
    const int row0 = blockIdx.x * 128;

    const uint32_t smb = smem_u32(sm);

    if (tid < D_SZ) bp_s[tid] = bp[tid];
    if (tid < T_SZ) { s_cnt[tid] = 0; sb_s[tid] = g_bs[tid]; }

    auto ldgA = [&](int ci, int h, float4* xr) {
        #pragma unroll
        for (int i = 0; i < 2; i++) {
            const int e   = (h * 2 + i) * 512 + tid;
            const int row = e >> 4;
            const int q4  = e & 15;
            float4 v = make_float4(0.f, 0.f, 0.f, 0.f);
            if (ci < 12 || q4 < 4)
                v = *(const float4*)(x + (size_t)(row0 + row) * DIN_SZ + ci * 64 + q4 * 4);
            xr[i] = v;
        }
    };
    auto stsA = [&](int h, int st, const float4* xr) {
        #pragma unroll
        for (int i = 0; i < 2; i++) {
            const int e   = (h * 2 + i) * 512 + tid;
            const int row = e >> 4;
            const int q4  = e & 15;
            const float vx = xr[i].x * XSCALE, vy = xr[i].y * XSCALE;
            const float vz = xr[i].z * XSCALE, vw = xr[i].w * XSCALE;
            __half h0 = __float2half_rn(vx), h1 = __float2half_rn(vy);
            __half h2 = __float2half_rn(vz), h3 = __float2half_rn(vw);
            uint2 hv, lv;
            hv.x = ((uint32_t)__half_as_ushort(h1) << 16) | __half_as_ushort(h0);
            hv.y = ((uint32_t)__half_as_ushort(h3) << 16) | __half_as_ushort(h2);
            lv.x = pack_h2(vx - __half2float(h0), vy - __half2float(h1));
            lv.y = pack_h2(vz - __half2float(h2), vw - __half2float(h3));
            const uint32_t off = SWZ128((uint32_t)(row * 128 + q4 * 8));
            *(uint2*)(sm + A_ST(st, 0) + off) = hv;
            *(uint2*)(sm + A_ST(st, 1) + off) = lv;
        }
    };
    auto issueB = [&](int ci, int st) {
        #pragma unroll
        for (int i = 0; i < 4; i++) {
            const int g = tid + i * 512;
            CP_ASYNC16(smb + B_ST(st) + g * 16, (const void*)&g_B16[0][ci][g]);
        }
        if (tid < 256) {
            const int sp = tid >> 7, g = tid & 127;
            CP_ASYNC16(smb + W_ST(st, sp) + g * 16, (const void*)&g_Ws16[sp][ci][g]);
        }
        CP_COMMIT();
    };

    // ---- fragment lane offsets ----
    uint32_t a_off[2], b_off[4], sa_off, ws_off;
    #pragma unroll
    for (int mt = 0; mt < 2; mt++)
        a_off[mt] = (uint32_t)((wm * 32 + mt * 16 + (lane & 15)) * 128 + (lane >> 4) * 16);
    #pragma unroll
    for (int np = 0; np < 4; np++) {
        const int bn = wn * 64 + np * 16 + ((lane >> 4) << 3) + (lane & 7);
        b_off[np] = (uint32_t)(bn * 128 + ((lane >> 3) & 1) * 16);
    }
    // strip rows: (wid & 7) * 16
    sa_off = (uint32_t)(((wid & 7) * 16 + (lane & 15)) * 128 + (lane >> 4) * 16);
    ws_off = (uint32_t)((((lane >> 4) << 3) + (lane & 7)) * 128 + ((lane >> 3) & 1) * 16);

    float acc[2][8][4];
    #pragma unroll
    for (int mt = 0; mt < 2; mt++)
        #pragma unroll
        for (int n8 = 0; n8 < 8; n8++)
            #pragma unroll
            for (int c = 0; c < 4; c++) acc[mt][n8][c] = 0.0f;
    float sacc[4];
    #pragma unroll
    for (int c = 0; c < 4; c++) sacc[c] = 0.0f;

    // ---- prologue ----
    issueB(0, 0);
    issueB(1, 1);
    {
        float4 xr[2];
        ldgA(0, 0, xr); stsA(0, 0, xr);
        ldgA(0, 1, xr); stsA(1, 0, xr);
    }
    CP_WAIT(1);
    __syncthreads();

    // ---- main loop ----
    for (int ci = 0; ci < NCHUNK; ci++) {
        const int st = ci & 1;
        const bool nx = (ci + 1 < NCHUNK);
        const uint32_t a_hi = smb + A_ST(st, 0);
        const uint32_t a_lo = smb + A_ST(st, 1);
        const uint32_t b_hi = smb + B_ST(st);
        const uint32_t w_hi = smb + W_ST(st, 0);
        const uint32_t w_lo = smb + W_ST(st, 1);

        float4 xr[2];
        if (nx) ldgA(ci + 1, 0, xr);

        #pragma unroll
        for (int ks = 0; ks < 4; ks++) {
            uint32_t ah[2][4];
            #pragma unroll
            for (int mt = 0; mt < 2; mt++)
                ldsm4(ah[mt], a_hi + SWZ128(a_off[mt] + ks * 32));

            // ---- single hi-B product (per-np tight) ----
            #pragma unroll
            for (int np = 0; np < 4; np++) {
                uint32_t r[4];
                ldsm4(r, b_hi + SWZ128(b_off[np] + ks * 32));
                #pragma unroll
                for (int mt = 0; mt < 2; mt++) {
                    mma16816(acc[mt][np * 2],     ah[mt], r);
                    mma16816(acc[mt][np * 2 + 1], ah[mt], r + 2);
                }
            }

            // ---- strip (all 16 warps): 3 products, 16 rows x n-half ----
            {
                uint32_t sah[4], sal[4];
                ldsm4(sah, a_hi + SWZ128(sa_off + ks * 32));
                ldsm4(sal, a_lo + SWZ128(sa_off + ks * 32));
                uint32_t wsh[2][2], wsl[2][2];
                {
                    uint32_t r[4];
                    ldsm4(r, w_hi + SWZ128(ws_off + ks * 32));
                    wsh[0][0] = r[0]; wsh[0][1] = r[1]; wsh[1][0] = r[2]; wsh[1][1] = r[3];
                    ldsm4(r, w_lo + SWZ128(ws_off + ks * 32));
                    wsl[0][0] = r[0]; wsl[0][1] = r[1]; wsl[1][0] = r[2]; wsl[1][1] = r[3];
                }
                mma16816(sacc, sah, wsh[nh]);
                mma16816(sacc, sah, wsl[nh]);
                mma16816(sacc, sal, wsh[nh]);
            }

            if (ks == 1 && nx) { stsA(0, st ^ 1, xr); ldgA(ci + 1, 1, xr); }
        }
        if (nx) stsA(1, st ^ 1, xr);

        __syncthreads();
        if (ci + 2 < NCHUNK) issueB(ci + 2, st);
        if (nx) { CP_WAIT(1); __syncthreads(); }
    }

    __syncthreads();   // done with operand smem; reuse for h staging

    // ---- epilogue: fragments -> fp16 hi/lo pairs in smem ----
    uint32_t* hsm32 = (uint32_t*)sm;
    #pragma unroll
    for (int mt = 0; mt < 2; mt++) {
        const int r_a = wm * 32 + mt * 16 + (lane >> 2);
        #pragma unroll
        for (int n8 = 0; n8 < 8; n8++) {
            const int col = wn * 64 + n8 * 8 + (lane & 3) * 2;
            #pragma unroll
            for (int hf = 0; hf < 2; hf++) {
                const int rr = r_a + hf * 8;
                float a0 = (acc[mt][n8][hf * 2]     * INVSCALE + bp_s[col])     * XSCALE;
                float a1 = (acc[mt][n8][hf * 2 + 1] * INVSCALE + bp_s[col + 1]) * XSCALE;
                __half h0 = __float2half_rn(a0), h1 = __float2half_rn(a1);
                uint32_t hv = ((uint32_t)__half_as_ushort(h1) << 16) | __half_as_ushort(h0);
                uint32_t lv = pack_h2(a0 - __half2float(h0), a1 - __half2float(h1));
                hsm32[rr * 128 + (col >> 1)]         = hv;
                hsm32[16384 + rr * 128 + (col >> 1)] = lv;
            }
        }
    }

    // ---- strip argmax: local best over this warp's 8 cols ----
    int   my_bt[2];
    float my_bv[2];
    int   my_row[2];
    {
        const int c0 = (lane & 3) * 2 + nh * 8;
        const float sb0 = sb_s[c0];
        const float sb1 = sb_s[c0 + 1];
        #pragma unroll
        for (int hf = 0; hf < 2; hf++) {
            float v0 = sacc[hf * 2]     + sb0;
            float v1 = sacc[hf * 2 + 1] + sb1;
            float bv = v0; int bi = c0;
            if (v1 > bv) { bv = v1; bi = c0 + 1; }
            #pragma unroll
            for (int d = 1; d <= 2; d <<= 1) {
                float ov = __shfl_xor_sync(0xffffffffu, bv, d);
                int   oi = __shfl_xor_sync(0xffffffffu, bi, d);
                if (ov > bv || (ov == bv && oi < bi)) { bv = ov; bi = oi; }
            }
            my_bv[hf] = bv;
            my_bt[hf] = bi;
            my_row[hf] = (wid & 7) * 16 + hf * 8 + (lane >> 2);
        }
    }
    const bool wlane = ((lane & 3) == 0);
    if (wid >= 8 && wlane) {
        #pragma unroll
        for (int hf = 0; hf < 2; hf++) {
            s_bv[my_row[hf]] = my_bv[hf];
            s_bi[my_row[hf]] = my_bt[hf];
        }
    }
    __syncthreads();

    int lpos[2];
    if (wid < 8 && wlane) {
        #pragma unroll
        for (int hf = 0; hf < 2; hf++) {
            const float ov = s_bv[my_row[hf]];
            const int   oi = s_bi[my_row[hf]];
            // high half owns cols 8-15 (> all low cols); tie -> lower index
            if (ov > my_bv[hf] || (ov == my_bv[hf] && oi < my_bt[hf]))
                my_bt[hf] = oi;
            lpos[hf] = atomicAdd(&s_cnt[my_bt[hf]], 1);
        }
    }
    __syncthreads();
    if (tid < T_SZ) s_base[tid] = atomicAdd(&g_counts[tid], s_cnt[tid]);
    __syncthreads();
    if (wid < 8 && wlane) {
        #pragma unroll
        for (int hf = 0; hf < 2; hf++) {
            const int r = row0 + my_row[hf];
            g_rowlist[my_bt[hf] * B_SZ + s_base[my_bt[hf]] + lpos[hf]] = r;
            if (write_idx) out_idx[r] = (float)my_bt[hf];
        }
    }

    // ---- spill hi/lo h to g_h16 (coalesced uint4) ----
    #pragma unroll
    for (int sp = 0; sp < 2; sp++) {
        #pragma unroll
        for (int i = 0; i < 8; i++) {
            const int e   = tid + i * 512;
            const int row = e >> 5, q4 = e & 31;
            ((uint4*)&g_h16[sp][row0 + row][0])[q4] =
                ((const uint4*)&hsm32[sp * 16384])[e];
        }
    }
}

// ========================================================================
// Kernel 2: HMMA routed classifier (R8, measured). CTA=(tile, 128 rows).
// ========================================================================
#define BM2 128
#define NT2 256
#define K2CH 4
#define A2_ST(st, sp) ((st) * 32768 + (sp) * 16384)
#define W2_ST(st, sp) (65536 + (st) * 16384 + (sp) * 8192)
#define SMEM2 98304

__global__ __launch_bounds__(NT2, 2)
void k2_classifier(const float* __restrict__ bc,
                   float* __restrict__ out)
{
    extern __shared__ char sm2[];
    __shared__ int rid_s[BM2];

    const int t    = blockIdx.y;
    const int cnt  = g_counts[t];
    const int base = blockIdx.x * BM2;
    if (base >= cnt) return;
    const int n = min(BM2, cnt - base);

    const int tid  = threadIdx.x;
    const int lane = tid & 31;
    const int wid  = tid >> 5;
    const int wm2  = wid >> 1;
    const int wn2  = wid & 1;
    const uint32_t smb = smem_u32(sm2);

    if (tid < BM2) {
        int idx = (tid < n) ? tid : (n - 1);
        rid_s[tid] = g_rowlist[t * B_SZ + base + idx];
    }
    __syncthreads();

    auto issue2 = [&](int ci, int st) {
        #pragma unroll
        for (int i = 0; i < 8; i++) {
            const int e   = tid + i * 256;
            const int sp  = e >> 10;
            const int rem = e & 1023;
            const int row = rem >> 3, q = rem & 7;
            const uint32_t dst = smb + A2_ST(st, sp) + SWZ128((uint32_t)(row * 128 + q * 16));
            CP_ASYNC16(dst, (const void*)&g_h16[sp][rid_s[row]][ci * 32 + q * 4]);
        }
        #pragma unroll
        for (int i = 0; i < 4; i++) {
            const int e  = tid + i * 256;
            const int sp = e >> 9, g = e & 511;
            CP_ASYNC16(smb + W2_ST(st, sp) + g * 16, (const void*)&g_Wc16[sp][t][ci][g]);
        }
        CP_COMMIT();
    };

    uint32_t a_off[2], b_off[2];
    #pragma unroll
    for (int mt = 0; mt < 2; mt++)
        a_off[mt] = (uint32_t)((wm2 * 32 + mt * 16 + (lane & 15)) * 128 + (lane >> 4) * 16);
    #pragma unroll
    for (int np = 0; np < 2; np++) {
        const int bn = wn2 * 32 + np * 16 + ((lane >> 4) << 3) + (lane & 7);
        b_off[np] = (uint32_t)(bn * 128 + ((lane >> 3) & 1) * 16);
    }

    float acc[2][4][4];
    #pragma unroll
    for (int mt = 0; mt < 2; mt++)
        #pragma unroll
        for (int n8 = 0; n8 < 4; n8++)
            #pragma unroll
            for (int c = 0; c < 4; c++) acc[mt][n8][c] = 0.0f;

    issue2(0, 0);
    issue2(1, 1);
    CP_WAIT(1);
    __syncthreads();

    for (int ci = 0; ci < K2CH; ci++) {
        const int st = ci & 1;
        const uint32_t a_hi = smb + A2_ST(st, 0);
        const uint32_t a_lo = smb + A2_ST(st, 1);
        const uint32_t w_hi = smb + W2_ST(st, 0);
        const uint32_t w_lo = smb + W2_ST(st, 1);

        #pragma unroll
        for (int ks = 0; ks < 4; ks++) {
            uint32_t ah[2][4], al[2][4];
            #pragma unroll
            for (int mt = 0; mt < 2; mt++) {
                ldsm4(ah[mt], a_hi + SWZ128(a_off[mt] + ks * 32));
                ldsm4(al[mt], a_lo + SWZ128(a_off[mt] + ks * 32));
            }
            uint32_t bh[4][2], bl[4][2];
            #pragma unroll
            for (int np = 0; np < 2; np++) {
                uint32_t r[4];
                ldsm4(r, w_hi + SWZ128(b_off[np] + ks * 32));
                bh[np * 2][0] = r[0]; bh[np * 2][1] = r[1];
                bh[np * 2 + 1][0] = r[2]; bh[np * 2 + 1][1] = r[3];
                ldsm4(r, w_lo + SWZ128(b_off[np] + ks * 32));
                bl[np * 2][0] = r[0]; bl[np * 2][1] = r[1];
                bl[np * 2 + 1][0] = r[2]; bl[np * 2 + 1][1] = r[3];
            }
            #pragma unroll
            for (int mt = 0; mt < 2; mt++)
                #pragma unroll
                for (int n8 = 0; n8 < 4; n8++) {
                    mma16816(acc[mt][n8], ah[mt], bh[n8]);
                    mma16816(acc[mt][n8], ah[mt], bl[n8]);
                    mma16816(acc[mt][n8], al[mt], bh[n8]);
                }
        }
        __syncthreads();
        if (ci + 2 < K2CH) issue2(ci + 2, st);
        if (ci + 1 < K2CH) { CP_WAIT(1); __syncthreads(); }
    }

    #pragma unroll
    for (int mt = 0; mt < 2; mt++) {
        const int r_a = wm2 * 32 + mt * 16 + (lane >> 2);
        #pragma unroll
        for (int n8 = 0; n8 < 4; n8++) {
            const int col = wn2 * 32 + n8 * 8 + (lane & 3) * 2;
            const float b0 = bc[t * C_SZ + col];
            const float b1 = bc[t * C_SZ + col + 1];
            #pragma unroll
            for (int hf = 0; hf < 2; hf++) {
                const int lr = r_a + hf * 8;
                if (lr < n) {
                    float2 v;
                    v.x = acc[mt][n8][hf * 2]     * INVSCALE + b0;
                    v.y = acc[mt][n8][hf * 2 + 1] * INVSCALE + b1;
                    *(float2*)(out + (size_t)rid_s[lr] * C_SZ + col) = v;
                }
            }
        }
    }
}

// ========================================================================
extern "C" void kernel_launch(void* const* d_in, const int* in_sizes, int n_in,
                              void* d_out, int out_size)
{
    const float* x    = (const float*)d_in[0];
    const float* Wp   = (const float*)d_in[1];
    const float* bp   = (const float*)d_in[2];
    const float* sigs = (const float*)d_in[3];
    const float* Wc   = (const float*)d_in[4];
    const float* bc   = (const float*)d_in[5];
    float* out = (float*)d_out;

    const int write_idx = (out_size >= B_SZ * C_SZ + B_SZ) ? 1 : 0;
    (void)in_sizes; (void)n_in;

    prep_all_kernel<<<142, 256>>>(Wp, bp, sigs, Wc);

    cudaFuncSetAttribute(k1_proj_route, cudaFuncAttributeMaxDynamicSharedMemorySize, SMEM1);
    k1_proj_route<<<NBLK, NT1, SMEM1>>>(x, bp, out + B_SZ * C_SZ, write_idx);

    cudaFuncSetAttribute(k2_classifier, cudaFuncAttributeMaxDynamicSharedMemorySize, SMEM2);
    dim3 g2(B_SZ / BM2, T_SZ);
    k2_classifier<<<g2, NT2, SMEM2>>>(bc, out);
}

// round 12
// speedup vs baseline: 1.1668x; 1.1668x over previous
#include <cuda_runtime.h>
#include <cuda_fp16.h>
#include <cstdint>

#define B_SZ 32768
#define DIN_SZ 784
#define D_SZ 256
#define T_SZ 16
#define C_SZ 64
#define NCHUNK 13            // K padded to 832, BK=64
#define NBLK (B_SZ / 128)

// ---------------- scratch (static __device__, no allocs) ----------------
__device__ uint32_t g_h16[2][B_SZ][128];     // h hi/lo fp16 pairs (x16 scaled)
__device__ int   g_rowlist[T_SZ * B_SZ];
__device__ int   g_counts[T_SZ];
__device__ uint4 g_B16[2][NCHUNK][2048];     // Wp^T hi/lo fp16 swizzled
__device__ uint4 g_Ws16[2][NCHUNK][128];     // Ws^T hi/lo fp16 swizzled
__device__ uint4 g_Wc16[2][T_SZ][4][512];    // Wc^T hi/lo fp16 swizzled per tile/chunk
__device__ float g_bs[T_SZ];                 // 1024 * (bp @ q(sigs)^T)

#define XSCALE 16.0f
#define WSCALE 64.0f
#define INVSCALE (1.0f / 1024.0f)

// ---------------- helpers ----------------
__device__ __forceinline__ uint32_t smem_u32(const void* p) {
    uint32_t a;
    asm("{ .reg .u64 t; cvta.to.shared.u64 t, %1; cvt.u32.u64 %0, t; }" : "=r"(a) : "l"(p));
    return a;
}
#define SWZ128(o) ((o) ^ (((o) >> 3) & 0x70))

#define CP_ASYNC16(dst, src) \
    asm volatile("cp.async.cg.shared.global [%0], [%1], 16;" :: "r"(dst), "l"(src))
#define CP_COMMIT() asm volatile("cp.async.commit_group;" ::: "memory")
#define CP_WAIT(n)  asm volatile("cp.async.wait_group %0;" :: "n"(n) : "memory")

__device__ __forceinline__ void ldsm4(uint32_t* r, uint32_t addr) {
    asm volatile("ldmatrix.sync.aligned.m8n8.x4.shared.b16 {%0,%1,%2,%3}, [%4];"
                 : "=r"(r[0]), "=r"(r[1]), "=r"(r[2]), "=r"(r[3]) : "r"(addr));
}
__device__ __forceinline__ void mma16816(float* c, const uint32_t* a, const uint32_t* b) {
    asm volatile("mma.sync.aligned.m16n8k16.row.col.f32.f16.f16.f32 "
                 "{%0,%1,%2,%3}, {%4,%5,%6,%7}, {%8,%9}, {%0,%1,%2,%3};"
                 : "+f"(c[0]), "+f"(c[1]), "+f"(c[2]), "+f"(c[3])
                 : "r"(a[0]), "r"(a[1]), "r"(a[2]), "r"(a[3]), "r"(b[0]), "r"(b[1]));
}
__device__ __forceinline__ uint32_t pack_h2(float a, float b) {
    __half h0 = __float2half_rn(a), h1 = __float2half_rn(b);
    return ((uint32_t)__half_as_ushort(h1) << 16) | __half_as_ushort(h0);
}

// ========================================================================
// Fused prep kernel (measured 23.7us in R11; ILP fix in Ws body):
// blockIdx [0,26) = prep_B halves; [26,90) = prep_Wc; [90,142) = prep_Ws.
// ========================================================================
__device__ void prep_B_body(int blk, const float* __restrict__ Wp, char* s_all) {
    float (*ws_s)[256] = (float(*)[256])s_all;
    const int ci   = blk >> 1;
    const int half = blk & 1;
    const int tid  = threadIdx.x;
    const int kbase = ci * 64 + half * 32;

    for (int e = tid; e < 2048; e += 256) {
        const int r = e >> 6, c4 = e & 63;
        const int k = kbase + r;
        float4 v = make_float4(0.f, 0.f, 0.f, 0.f);
        if (k < DIN_SZ) v = ((const float4*)(Wp + (size_t)k * D_SZ))[c4];
        *(float4*)&ws_s[r][c4 * 4] = v;
    }
    __syncthreads();

    #pragma unroll
    for (int i = 0; i < 4; i++) {
        const int e  = tid + i * 256;
        const int n  = e & 255;
        const int kq = e >> 8;
        float v[8], h[8];
        #pragma unroll
        for (int j = 0; j < 8; j++) {
            v[j] = ws_s[kq * 8 + j][n] * WSCALE;
            h[j] = __half2float(__float2half_rn(v[j]));
        }
        uint4 hi, lo;
        hi.x = pack_h2(v[0], v[1]); hi.y = pack_h2(v[2], v[3]);
        hi.z = pack_h2(v[4], v[5]); hi.w = pack_h2(v[6], v[7]);
        lo.x = pack_h2(v[0] - h[0], v[1] - h[1]); lo.y = pack_h2(v[2] - h[2], v[3] - h[3]);
        lo.z = pack_h2(v[4] - h[4], v[5] - h[5]); lo.w = pack_h2(v[6] - h[6], v[7] - h[7]);
        const uint32_t off = SWZ128((uint32_t)(n * 128 + (half * 4 + kq) * 16));
        g_B16[0][ci][off >> 4] = hi;
        g_B16[1][ci][off >> 4] = lo;
    }
}

__device__ void prep_Wc_body(int blk, const float* __restrict__ Wc, char* s_all) {
    float (*wc_s)[64] = (float(*)[64])s_all;
    const int t   = blk >> 2;
    const int ci  = blk & 3;
    const int tid = threadIdx.x;

    #pragma unroll
    for (int i = 0; i < 4; i++) {
        const int e = tid + i * 256;
        const int r = e >> 4, c4 = e & 15;
        *(float4*)&wc_s[r][c4 * 4] =
            ((const float4*)(Wc + ((size_t)t * 256 + ci * 64 + r) * C_SZ))[c4];
    }
    __syncthreads();

    #pragma unroll
    for (int i = 0; i < 2; i++) {
        const int e = tid + i * 256;
        const int n = e >> 3, q = e & 7;
        float v[8], h[8];
        #pragma unroll
        for (int j = 0; j < 8; j++) {
            v[j] = wc_s[q * 8 + j][n] * WSCALE;
            h[j] = __half2float(__float2half_rn(v[j]));
        }
        uint4 hi, lo;
        hi.x = pack_h2(v[0], v[1]); hi.y = pack_h2(v[2], v[3]);
        hi.z = pack_h2(v[4], v[5]); hi.w = pack_h2(v[6], v[7]);
        lo.x = pack_h2(v[0] - h[0], v[1] - h[1]); lo.y = pack_h2(v[2] - h[2], v[3] - h[3]);
        lo.z = pack_h2(v[4] - h[4], v[5] - h[5]); lo.w = pack_h2(v[6] - h[6], v[7] - h[7]);
        const uint32_t off = SWZ128((uint32_t)(n * 128 + q * 16));
        g_Wc16[0][t][ci][off >> 4] = hi;
        g_Wc16[1][t][ci][off >> 4] = lo;
    }
}

__device__ void prep_Ws_body(int blk, const float* __restrict__ Wp,
                             const float* __restrict__ bp,
                             const float* __restrict__ sigs_raw, char* s_all) {
    float (*q_s)[257] = (float(*)[257])s_all;                    // [16][257]
    float (*w_s)[257] = (float(*)[257])(s_all + 16 * 257 * 4);   // [16][257]
    const int tid = threadIdx.x;
    const int k0  = blk * 16;

    if (blk == 0 && tid < T_SZ) g_counts[tid] = 0;

    for (int e = tid; e < T_SZ * D_SZ; e += 256) {
        const int t = e >> 8, d = e & 255;
        float s = sigs_raw[e];
        q_s[t][d] = (s > 0.3f) ? 1.0f : ((s < -0.3f) ? -1.0f : 0.0f);
    }
    for (int e = tid; e < 16 * D_SZ; e += 256) {
        const int r = e >> 8, d = e & 255;
        const int k = k0 + r;
        w_s[r][d] = (k < DIN_SZ) ? Wp[(size_t)k * D_SZ + d] : 0.f;
    }
    __syncthreads();

    const int ty = tid >> 4;       // 0..15
    const int t  = tid & 15;
    const int k  = k0 + ty;
    // 4-way ILP-split dot (breaks 1024-cycle serial FMA chain)
    float a0 = 0.f, a1 = 0.f, a2 = 0.f, a3 = 0.f;
    #pragma unroll 8
    for (int d = 0; d < D_SZ; d += 4) {
        a0 += w_s[ty][d]     * q_s[t][d];
        a1 += w_s[ty][d + 1] * q_s[t][d + 1];
        a2 += w_s[ty][d + 2] * q_s[t][d + 2];
        a3 += w_s[ty][d + 3] * q_s[t][d + 3];
    }
    float acc = (a0 + a1) + (a2 + a3);

    acc *= WSCALE;
    __half hi = __float2half_rn(acc);
    __half lo = __float2half_rn(acc - __half2float(hi));
    const int ci = k >> 6, kin = k & 63;
    const uint32_t off = SWZ128((uint32_t)(t * 128 + kin * 2));
    *(unsigned short*)((char*)g_Ws16[0][ci] + off) = __half_as_ushort(hi);
    *(unsigned short*)((char*)g_Ws16[1][ci] + off) = __half_as_ushort(lo);

    if (blk == 0 && tid < T_SZ) {
        float b0 = 0.f, b1 = 0.f, b2 = 0.f, b3 = 0.f;
        for (int d = 0; d < D_SZ; d += 4) {
            b0 += bp[d]     * q_s[tid][d];
            b1 += bp[d + 1] * q_s[tid][d + 1];
            b2 += bp[d + 2] * q_s[tid][d + 2];
            b3 += bp[d + 3] * q_s[tid][d + 3];
        }
        g_bs[tid] = ((b0 + b1) + (b2 + b3)) * (XSCALE * WSCALE);
    }
}

__global__ __launch_bounds__(256)
void prep_all_kernel(const float* __restrict__ Wp,
                     const float* __restrict__ bp,
                     const float* __restrict__ sigs_raw,
                     const float* __restrict__ Wc) {
    __shared__ __align__(16) char s_all[33024];
    const int b = blockIdx.x;
    if (b < 26)       prep_B_body(b, Wp, s_all);
    else if (b < 90)  prep_Wc_body(b - 26, Wc, s_all);
    else              prep_Ws_body(b - 90, Wp, bp, sigs_raw, s_all);
}

// ========================================================================
// Kernel 1: EXACT R10 version (measured 82.1us).
// 512 threads / 16 warps (4M x 4N), warp tile 32x64, BK=64.
// Single-product h GEMM (x_hi . W_hi); 3-product strip on warps 0-7.
// ========================================================================
#define NT1 512
#define SMEM1 139264
#define A_ST(st, sp) ((st) * 32768 + (sp) * 16384)
#define B_ST(st)     (65536 + (st) * 32768)
#define W_ST(st, sp) (131072 + (st) * 4096 + (sp) * 2048)

__global__ __launch_bounds__(NT1, 1)
void k1_proj_route(const float* __restrict__ x,
                   const float* __restrict__ bp,
                   float* __restrict__ out_idx,
                   int write_idx)
{
    extern __shared__ char sm[];
    __shared__ float bp_s[D_SZ];
    __shared__ float sb_s[T_SZ];
    __shared__ int s_cnt[T_SZ];
    __shared__ int s_base[T_SZ];

    const int tid  = threadIdx.x;
    const int lane = tid & 31;
    const int wid  = tid >> 5;
    const int wm   = wid >> 2;          // 0..3 (32-row groups)
    const int wn   = wid & 3;           // 0..3 (64-col groups)
    const int row0 = blockIdx.x * 128;

    const uint32_t smb = smem_u32(sm);

    if (tid < D_SZ) bp_s[tid] = bp[tid];
    if (tid < T_SZ) { s_cnt[tid] = 0; sb_s[tid] = g_bs[tid]; }

    auto ldgA = [&](int ci, int h, float4* xr) {
        #pragma unroll
        for (int i = 0; i < 2; i++) {
            const int e   = (h * 2 + i) * 512 + tid;
            const int row = e >> 4;
            const int q4  = e & 15;
            float4 v = make_float4(0.f, 0.f, 0.f, 0.f);
            if (ci < 12 || q4 < 4)
                v = *(const float4*)(x + (size_t)(row0 + row) * DIN_SZ + ci * 64 + q4 * 4);
            xr[i] = v;
        }
    };
    auto stsA = [&](int h, int st, const float4* xr) {
        #pragma unroll
        for (int i = 0; i < 2; i++) {
            const int e   = (h * 2 + i) * 512 + tid;
            const int row = e >> 4;
            const int q4  = e & 15;
            const float vx = xr[i].x * XSCALE, vy = xr[i].y * XSCALE;
            const float vz = xr[i].z * XSCALE, vw = xr[i].w * XSCALE;
            __half h0 = __float2half_rn(vx), h1 = __float2half_rn(vy);
            __half h2 = __float2half_rn(vz), h3 = __float2half_rn(vw);
            uint2 hv, lv;
            hv.x = ((uint32_t)__half_as_ushort(h1) << 16) | __half_as_ushort(h0);
            hv.y = ((uint32_t)__half_as_ushort(h3) << 16) | __half_as_ushort(h2);
            lv.x = pack_h2(vx - __half2float(h0), vy - __half2float(h1));
            lv.y = pack_h2(vz - __half2float(h2), vw - __half2float(h3));
            const uint32_t off = SWZ128((uint32_t)(row * 128 + q4 * 8));
            *(uint2*)(sm + A_ST(st, 0) + off) = hv;
            *(uint2*)(sm + A_ST(st, 1) + off) = lv;
        }
    };
    auto issueB = [&](int ci, int st) {
        #pragma unroll
        for (int i = 0; i < 4; i++) {
            const int g = tid + i * 512;
            CP_ASYNC16(smb + B_ST(st) + g * 16, (const void*)&g_B16[0][ci][g]);
        }
        if (tid < 256) {
            const int sp = tid >> 7, g = tid & 127;
            CP_ASYNC16(smb + W_ST(st, sp) + g * 16, (const void*)&g_Ws16[sp][ci][g]);
        }
        CP_COMMIT();
    };

    // ---- fragment lane offsets ----
    uint32_t a_off[2], b_off[4], sa_off, ws_off;
    #pragma unroll
    for (int mt = 0; mt < 2; mt++)
        a_off[mt] = (uint32_t)((wm * 32 + mt * 16 + (lane & 15)) * 128 + (lane >> 4) * 16);
    #pragma unroll
    for (int np = 0; np < 4; np++) {
        const int bn = wn * 64 + np * 16 + ((lane >> 4) << 3) + (lane & 7);
        b_off[np] = (uint32_t)(bn * 128 + ((lane >> 3) & 1) * 16);
    }
    // strip: warps 0-7 own rows wid*16 .. wid*16+15
    sa_off = (uint32_t)((wid * 16 + (lane & 15)) * 128 + (lane >> 4) * 16);
    ws_off = (uint32_t)((((lane >> 4) << 3) + (lane & 7)) * 128 + ((lane >> 3) & 1) * 16);

    float acc[2][8][4];
    #pragma unroll
    for (int mt = 0; mt < 2; mt++)
        #pragma unroll
        for (int n8 = 0; n8 < 8; n8++)
            #pragma unroll
            for (int c = 0; c < 4; c++) acc[mt][n8][c] = 0.0f;
    float sacc[2][4];
    #pragma unroll
    for (int n8 = 0; n8 < 2; n8++)
        #pragma unroll
        for (int c = 0; c < 4; c++) sacc[n8][c] = 0.0f;

    // ---- prologue ----
    issueB(0, 0);
    issueB(1, 1);
    {
        float4 xr[2];
        ldgA(0, 0, xr); stsA(0, 0, xr);
        ldgA(0, 1, xr); stsA(1, 0, xr);
    }
    CP_WAIT(1);
    __syncthreads();

    // ---- main loop ----
    for (int ci = 0; ci < NCHUNK; ci++) {
        const int st = ci & 1;
        const bool nx = (ci + 1 < NCHUNK);
        const uint32_t a_hi = smb + A_ST(st, 0);
        const uint32_t a_lo = smb + A_ST(st, 1);
        const uint32_t b_hi = smb + B_ST(st);
        const uint32_t w_hi = smb + W_ST(st, 0);
        const uint32_t w_lo = smb + W_ST(st, 1);

        float4 xr[2];
        if (nx) ldgA(ci + 1, 0, xr);

        #pragma unroll
        for (int ks = 0; ks < 4; ks++) {
            uint32_t ah[2][4];
            #pragma unroll
            for (int mt = 0; mt < 2; mt++)
                ldsm4(ah[mt], a_hi + SWZ128(a_off[mt] + ks * 32));

            // ---- single hi-B product (per-np tight) ----
            #pragma unroll
            for (int np = 0; np < 4; np++) {
                uint32_t r[4];
                ldsm4(r, b_hi + SWZ128(b_off[np] + ks * 32));
                #pragma unroll
                for (int mt = 0; mt < 2; mt++) {
                    mma16816(acc[mt][np * 2],     ah[mt], r);
                    mma16816(acc[mt][np * 2 + 1], ah[mt], r + 2);
                }
            }

            // ---- strip (warps 0-7): 3 products on 16 rows ----
            if (wid < 8) {
                uint32_t sah[4], sal[4];
                ldsm4(sah, a_hi + SWZ128(sa_off + ks * 32));
                ldsm4(sal, a_lo + SWZ128(sa_off + ks * 32));
                uint32_t wsh[2][2], wsl[2][2];
                {
                    uint32_t r[4];
                    ldsm4(r, w_hi + SWZ128(ws_off + ks * 32));
                    wsh[0][0] = r[0]; wsh[0][1] = r[1]; wsh[1][0] = r[2]; wsh[1][1] = r[3];
                    ldsm4(r, w_lo + SWZ128(ws_off + ks * 32));
                    wsl[0][0] = r[0]; wsl[0][1] = r[1]; wsl[1][0] = r[2]; wsl[1][1] = r[3];
                }
                #pragma unroll
                for (int n8 = 0; n8 < 2; n8++) {
                    mma16816(sacc[n8], sah, wsh[n8]);
                    mma16816(sacc[n8], sah, wsl[n8]);
                    mma16816(sacc[n8], sal, wsh[n8]);
                }
            }

            if (ks == 1 && nx) { stsA(0, st ^ 1, xr); ldgA(ci + 1, 1, xr); }
        }
        if (nx) stsA(1, st ^ 1, xr);

        __syncthreads();
        if (ci + 2 < NCHUNK) issueB(ci + 2, st);
        if (nx) { CP_WAIT(1); __syncthreads(); }
    }

    __syncthreads();   // done with operand smem; reuse for h staging

    // ---- epilogue: fragments -> fp16 hi/lo pairs in smem ----
    uint32_t* hsm32 = (uint32_t*)sm;
    #pragma unroll
    for (int mt = 0; mt < 2; mt++) {
        const int r_a = wm * 32 + mt * 16 + (lane >> 2);
        #pragma unroll
        for (int n8 = 0; n8 < 8; n8++) {
            const int col = wn * 64 + n8 * 8 + (lane & 3) * 2;
            #pragma unroll
            for (int hf = 0; hf < 2; hf++) {
                const int rr = r_a + hf * 8;
                float a0 = (acc[mt][n8][hf * 2]     * INVSCALE + bp_s[col])     * XSCALE;
                float a1 = (acc[mt][n8][hf * 2 + 1] * INVSCALE + bp_s[col + 1]) * XSCALE;
                __half h0 = __float2half_rn(a0), h1 = __float2half_rn(a1);
                uint32_t hv = ((uint32_t)__half_as_ushort(h1) << 16) | __half_as_ushort(h0);
                uint32_t lv = pack_h2(a0 - __half2float(h0), a1 - __half2float(h1));
                hsm32[rr * 128 + (col >> 1)]         = hv;
                hsm32[16384 + rr * 128 + (col >> 1)] = lv;
            }
        }
    }

    // ---- strip argmax (warps 0-7; rows wid*16..wid*16+15) ----
    int   my_bt[2];
    int   my_row[2];
    const bool writer = (wid < 8) && ((lane & 3) == 0);
    if (wid < 8) {
        const int c0 = (lane & 3) * 2;
        const float sb0 = sb_s[c0];
        const float sb1 = sb_s[c0 + 1];
        const float sb2 = sb_s[c0 + 8];
        const float sb3 = sb_s[c0 + 9];
        #pragma unroll
        for (int hf = 0; hf < 2; hf++) {
            float v0 = sacc[0][hf * 2]     + sb0;
            float v1 = sacc[0][hf * 2 + 1] + sb1;
            float v2 = sacc[1][hf * 2]     + sb2;
            float v3 = sacc[1][hf * 2 + 1] + sb3;
            float bv = v0; int bi = c0;
            if (v1 > bv) { bv = v1; bi = c0 + 1; }
            if (v2 > bv) { bv = v2; bi = c0 + 8; }
            if (v3 > bv) { bv = v3; bi = c0 + 9; }
            #pragma unroll
            for (int d = 1; d <= 2; d <<= 1) {
                float ov = __shfl_xor_sync(0xffffffffu, bv, d);
                int   oi = __shfl_xor_sync(0xffffffffu, bi, d);
                if (ov > bv || (ov == bv && oi < bi)) { bv = ov; bi = oi; }
            }
            my_bt[hf]  = bi;
            my_row[hf] = wid * 16 + hf * 8 + (lane >> 2);
        }
    }

    int lpos[2];
    if (writer) {
        #pragma unroll
        for (int q = 0; q < 2; q++)
            lpos[q] = atomicAdd(&s_cnt[my_bt[q]], 1);
    }
    __syncthreads();
    if (tid < T_SZ) s_base[tid] = atomicAdd(&g_counts[tid], s_cnt[tid]);
    __syncthreads();
    if (writer) {
        #pragma unroll
        for (int q = 0; q < 2; q++) {
            const int r = row0 + my_row[q];
            g_rowlist[my_bt[q] * B_SZ + s_base[my_bt[q]] + lpos[q]] = r;
            if (write_idx) out_idx[r] = (float)my_bt[q];
        }
    }

    // ---- spill hi/lo h to g_h16 (coalesced uint4) ----
    #pragma unroll
    for (int sp = 0; sp < 2; sp++) {
        #pragma unroll
        for (int i = 0; i < 8; i++) {
            const int e   = tid + i * 512;
            const int row = e >> 5, q4 = e & 31;
            ((uint4*)&g_h16[sp][row0 + row][0])[q4] =
                ((const uint4*)&hsm32[sp * 16384])[e];
        }
    }
}

// ========================================================================
// Kernel 2: HMMA routed classifier (R8, measured). CTA=(tile, 128 rows).
// ========================================================================
#define BM2 128
#define NT2 256
#define K2CH 4
#define A2_ST(st, sp) ((st) * 32768 + (sp) * 16384)
#define W2_ST(st, sp) (65536 + (st) * 16384 + (sp) * 8192)
#define SMEM2 98304

__global__ __launch_bounds__(NT2, 2)
void k2_classifier(const float* __restrict__ bc,
                   float* __restrict__ out)
{
    extern __shared__ char sm2[];
    __shared__ int rid_s[BM2];

    const int t    = blockIdx.y;
    const int cnt  = g_counts[t];
    const int base = blockIdx.x * BM2;
    if (base >= cnt) return;
    const int n = min(BM2, cnt - base);

    const int tid  = threadIdx.x;
    const int lane = tid & 31;
    const int wid  = tid >> 5;
    const int wm2  = wid >> 1;
    const int wn2  = wid & 1;
    const uint32_t smb = smem_u32(sm2);

    if (tid < BM2) {
        int idx = (tid < n) ? tid : (n - 1);
        rid_s[tid] = g_rowlist[t * B_SZ + base + idx];
    }
    __syncthreads();

    auto issue2 = [&](int ci, int st) {
        #pragma unroll
        for (int i = 0; i < 8; i++) {
            const int e   = tid + i * 256;
            const int sp  = e >> 10;
            const int rem = e & 1023;
            const int row = rem >> 3, q = rem & 7;
            const uint32_t dst = smb + A2_ST(st, sp) + SWZ128((uint32_t)(row * 128 + q * 16));
            CP_ASYNC16(dst, (const void*)&g_h16[sp][rid_s[row]][ci * 32 + q * 4]);
        }
        #pragma unroll
        for (int i = 0; i < 4; i++) {
            const int e  = tid + i * 256;
            const int sp = e >> 9, g = e & 511;
            CP_ASYNC16(smb + W2_ST(st, sp) + g * 16, (const void*)&g_Wc16[sp][t][ci][g]);
        }
        CP_COMMIT();
    };

    uint32_t a_off[2], b_off[2];
    #pragma unroll
    for (int mt = 0; mt < 2; mt++)
        a_off[mt] = (uint32_t)((wm2 * 32 + mt * 16 + (lane & 15)) * 128 + (lane >> 4) * 16);
    #pragma unroll
    for (int np = 0; np < 2; np++) {
        const int bn = wn2 * 32 + np * 16 + ((lane >> 4) << 3) + (lane & 7);
        b_off[np] = (uint32_t)(bn * 128 + ((lane >> 3) & 1) * 16);
    }

    float acc[2][4][4];
    #pragma unroll
    for (int mt = 0; mt < 2; mt++)
        #pragma unroll
        for (int n8 = 0; n8 < 4; n8++)
            #pragma unroll
            for (int c = 0; c < 4; c++) acc[mt][n8][c] = 0.0f;

    issue2(0, 0);
    issue2(1, 1);
    CP_WAIT(1);
    __syncthreads();

    for (int ci = 0; ci < K2CH; ci++) {
        const int st = ci & 1;
        const uint32_t a_hi = smb + A2_ST(st, 0);
        const uint32_t a_lo = smb + A2_ST(st, 1);
        const uint32_t w_hi = smb + W2_ST(st, 0);
        const uint32_t w_lo = smb + W2_ST(st, 1);

        #pragma unroll
        for (int ks = 0; ks < 4; ks++) {
            uint32_t ah[2][4], al[2][4];
            #pragma unroll
            for (int mt = 0; mt < 2; mt++) {
                ldsm4(ah[mt], a_hi + SWZ128(a_off[mt] + ks * 32));
                ldsm4(al[mt], a_lo + SWZ128(a_off[mt] + ks * 32));
            }
            uint32_t bh[4][2], bl[4][2];
            #pragma unroll
            for (int np = 0; np < 2; np++) {
                uint32_t r[4];
                ldsm4(r, w_hi + SWZ128(b_off[np] + ks * 32));
                bh[np * 2][0] = r[0]; bh[np * 2][1] = r[1];
                bh[np * 2 + 1][0] = r[2]; bh[np * 2 + 1][1] = r[3];
                ldsm4(r, w_lo + SWZ128(b_off[np] + ks * 32));
                bl[np * 2][0] = r[0]; bl[np * 2][1] = r[1];
                bl[np * 2 + 1][0] = r[2]; bl[np * 2 + 1][1] = r[3];
            }
            #pragma unroll
            for (int mt = 0; mt < 2; mt++)
                #pragma unroll
                for (int n8 = 0; n8 < 4; n8++) {
                    mma16816(acc[mt][n8], ah[mt], bh[n8]);
                    mma16816(acc[mt][n8], ah[mt], bl[n8]);
                    mma16816(acc[mt][n8], al[mt], bh[n8]);
                }
        }
        __syncthreads();
        if (ci + 2 < K2CH) issue2(ci + 2, st);
        if (ci + 1 < K2CH) { CP_WAIT(1); __syncthreads(); }
    }

    #pragma unroll
    for (int mt = 0; mt < 2; mt++) {
        const int r_a = wm2 * 32 + mt * 16 + (lane >> 2);
        #pragma unroll
        for (int n8 = 0; n8 < 4; n8++) {
            const int col = wn2 * 32 + n8 * 8 + (lane & 3) * 2;
            const float b0 = bc[t * C_SZ + col];
            const float b1 = bc[t * C_SZ + col + 1];
            #pragma unroll
            for (int hf = 0; hf < 2; hf++) {
                const int lr = r_a + hf * 8;
                if (lr < n) {
                    float2 v;
                    v.x = acc[mt][n8][hf * 2]     * INVSCALE + b0;
                    v.y = acc[mt][n8][hf * 2 + 1] * INVSCALE + b1;
                    *(float2*)(out + (size_t)rid_s[lr] * C_SZ + col) = v;
                }
            }
        }
    }
}

// ========================================================================
extern "C" void kernel_launch(void* const* d_in, const int* in_sizes, int n_in,
                              void* d_out, int out_size)
{
    const float* x    = (const float*)d_in[0];
    const float* Wp   = (const float*)d_in[1];
    const float* bp   = (const float*)d_in[2];
    const float* sigs = (const float*)d_in[3];
    const float* Wc   = (const float*)d_in[4];
    const float* bc   = (const float*)d_in[5];
    float* out = (float*)d_out;

    const int write_idx = (out_size >= B_SZ * C_SZ + B_SZ) ? 1 : 0;
    (void)in_sizes; (void)n_in;

    prep_all_kernel<<<142, 256>>>(Wp, bp, sigs, Wc);

    cudaFuncSetAttribute(k1_proj_route, cudaFuncAttributeMaxDynamicSharedMemorySize, SMEM1);
    k1_proj_route<<<NBLK, NT1, SMEM1>>>(x, bp, out + B_SZ * C_SZ, write_idx);

    cudaFuncSetAttribute(k2_classifier, cudaFuncAttributeMaxDynamicSharedMemorySize, SMEM2);
    dim3 g2(B_SZ / BM2, T_SZ);
    k2_classifier<<<g2, NT2, SMEM2>>>(bc, out);
}

// round 14
// speedup vs baseline: 1.1871x; 1.0175x over previous
#include <cuda_runtime.h>
#include <cuda_fp16.h>
#include <cstdint>

#define B_SZ 32768
#define DIN_SZ 784
#define D_SZ 256
#define T_SZ 16
#define C_SZ 64
#define NCHUNK 13            // K padded to 832, BK=64
#define NBLK (B_SZ / 128)

// ---------------- scratch (static __device__, no allocs) ----------------
__device__ uint32_t g_h16[2][B_SZ][128];     // h hi/lo fp16 pairs (x16 scaled)
__device__ int   g_rowlist[T_SZ * B_SZ];
__device__ int   g_counts[T_SZ];
__device__ uint4 g_B16[2][NCHUNK][2048];     // Wp^T hi/lo fp16 swizzled
__device__ uint4 g_Ws16[2][NCHUNK][128];     // Ws^T hi/lo fp16 swizzled
__device__ uint4 g_Wc16[2][T_SZ][4][512];    // Wc^T hi/lo fp16 swizzled per tile/chunk
__device__ float g_bs[T_SZ];                 // 1024 * (bp @ q(sigs)^T)

#define XSCALE 16.0f
#define WSCALE 64.0f
#define INVSCALE (1.0f / 1024.0f)

// ---------------- helpers ----------------
__device__ __forceinline__ uint32_t smem_u32(const void* p) {
    uint32_t a;
    asm("{ .reg .u64 t; cvta.to.shared.u64 t, %1; cvt.u32.u64 %0, t; }" : "=r"(a) : "l"(p));
    return a;
}
#define SWZ128(o) ((o) ^ (((o) >> 3) & 0x70))

#define CP_ASYNC16(dst, src) \
    asm volatile("cp.async.cg.shared.global [%0], [%1], 16;" :: "r"(dst), "l"(src))
#define CP_COMMIT() asm volatile("cp.async.commit_group;" ::: "memory")
#define CP_WAIT(n)  asm volatile("cp.async.wait_group %0;" :: "n"(n) : "memory")

__device__ __forceinline__ void ldsm4(uint32_t* r, uint32_t addr) {
    asm volatile("ldmatrix.sync.aligned.m8n8.x4.shared.b16 {%0,%1,%2,%3}, [%4];"
                 : "=r"(r[0]), "=r"(r[1]), "=r"(r[2]), "=r"(r[3]) : "r"(addr));
}
__device__ __forceinline__ void mma16816(float* c, const uint32_t* a, const uint32_t* b) {
    asm volatile("mma.sync.aligned.m16n8k16.row.col.f32.f16.f16.f32 "
                 "{%0,%1,%2,%3}, {%4,%5,%6,%7}, {%8,%9}, {%0,%1,%2,%3};"
                 : "+f"(c[0]), "+f"(c[1]), "+f"(c[2]), "+f"(c[3])
                 : "r"(a[0]), "r"(a[1]), "r"(a[2]), "r"(a[3]), "r"(b[0]), "r"(b[1]));
}
__device__ __forceinline__ uint32_t pack_h2(float a, float b) {
    __half h0 = __float2half_rn(a), h1 = __float2half_rn(b);
    return ((uint32_t)__half_as_ushort(h1) << 16) | __half_as_ushort(h0);
}

// ========================================================================
// Fused prep kernel: [0,26) prep_B; [26,90) prep_Wc; [90,194) prep_Ws
// (Ws split into 104 blocks of 8 k-rows, 2 threads per output).
// ========================================================================
__device__ void prep_B_body(int blk, const float* __restrict__ Wp, char* s_all) {
    float (*ws_s)[256] = (float(*)[256])s_all;
    const int ci   = blk >> 1;
    const int half = blk & 1;
    const int tid  = threadIdx.x;
    const int kbase = ci * 64 + half * 32;

    for (int e = tid; e < 2048; e += 256) {
        const int r = e >> 6, c4 = e & 63;
        const int k = kbase + r;
        float4 v = make_float4(0.f, 0.f, 0.f, 0.f);
        if (k < DIN_SZ) v = ((const float4*)(Wp + (size_t)k * D_SZ))[c4];
        *(float4*)&ws_s[r][c4 * 4] = v;
    }
    __syncthreads();

    #pragma unroll
    for (int i = 0; i < 4; i++) {
        const int e  = tid + i * 256;
        const int n  = e & 255;
        const int kq = e >> 8;
        float v[8], h[8];
        #pragma unroll
        for (int j = 0; j < 8; j++) {
            v[j] = ws_s[kq * 8 + j][n] * WSCALE;
            h[j] = __half2float(__float2half_rn(v[j]));
        }
        uint4 hi, lo;
        hi.x = pack_h2(v[0], v[1]); hi.y = pack_h2(v[2], v[3]);
        hi.z = pack_h2(v[4], v[5]); hi.w = pack_h2(v[6], v[7]);
        lo.x = pack_h2(v[0] - h[0], v[1] - h[1]); lo.y = pack_h2(v[2] - h[2], v[3] - h[3]);
        lo.z = pack_h2(v[4] - h[4], v[5] - h[5]); lo.w = pack_h2(v[6] - h[6], v[7] - h[7]);
        const uint32_t off = SWZ128((uint32_t)(n * 128 + (half * 4 + kq) * 16));
        g_B16[0][ci][off >> 4] = hi;
        g_B16[1][ci][off >> 4] = lo;
    }
}

__device__ void prep_Wc_body(int blk, const float* __restrict__ Wc, char* s_all) {
    float (*wc_s)[64] = (float(*)[64])s_all;
    const int t   = blk >> 2;
    const int ci  = blk & 3;
    const int tid = threadIdx.x;

    #pragma unroll
    for (int i = 0; i < 4; i++) {
        const int e = tid + i * 256;
        const int r = e >> 4, c4 = e & 15;
        *(float4*)&wc_s[r][c4 * 4] =
            ((const float4*)(Wc + ((size_t)t * 256 + ci * 64 + r) * C_SZ))[c4];
    }
    __syncthreads();

    #pragma unroll
    for (int i = 0; i < 2; i++) {
        const int e = tid + i * 256;
        const int n = e >> 3, q = e & 7;
        float v[8], h[8];
        #pragma unroll
        for (int j = 0; j < 8; j++) {
            v[j] = wc_s[q * 8 + j][n] * WSCALE;
            h[j] = __half2float(__float2half_rn(v[j]));
        }
        uint4 hi, lo;
        hi.x = pack_h2(v[0], v[1]); hi.y = pack_h2(v[2], v[3]);
        hi.z = pack_h2(v[4], v[5]); hi.w = pack_h2(v[6], v[7]);
        lo.x = pack_h2(v[0] - h[0], v[1] - h[1]); lo.y = pack_h2(v[2] - h[2], v[3] - h[3]);
        lo.z = pack_h2(v[4] - h[4], v[5] - h[5]); lo.w = pack_h2(v[6] - h[6], v[7] - h[7]);
        const uint32_t off = SWZ128((uint32_t)(n * 128 + q * 16));
        g_Wc16[0][t][ci][off >> 4] = hi;
        g_Wc16[1][t][ci][off >> 4] = lo;
    }
}

// Ws: 104 blocks x 8 k-rows; 2 threads per (k,t) output, d-range split,
// combine via shfl_xor(1). Shorter per-block critical path.
__device__ void prep_Ws_body(int blk, const float* __restrict__ Wp,
                             const float* __restrict__ bp,
                             const float* __restrict__ sigs_raw, char* s_all) {
    float (*q_s)[257] = (float(*)[257])s_all;                    // [16][257]
    float (*w_s)[257] = (float(*)[257])(s_all + 16 * 257 * 4);   // [8][257]
    const int tid = threadIdx.x;
    const int k0  = blk * 8;

    if (blk == 0 && tid < T_SZ) g_counts[tid] = 0;

    for (int e = tid; e < T_SZ * D_SZ; e += 256) {
        const int t = e >> 8, d = e & 255;
        float s = sigs_raw[e];
        q_s[t][d] = (s > 0.3f) ? 1.0f : ((s < -0.3f) ? -1.0f : 0.0f);
    }
    for (int e = tid; e < 8 * D_SZ; e += 256) {
        const int r = e >> 8, d = e & 255;
        const int k = k0 + r;
        w_s[r][d] = (k < DIN_SZ) ? Wp[(size_t)k * D_SZ + d] : 0.f;
    }
    __syncthreads();

    const int out  = tid >> 1;          // 0..127
    const int half = tid & 1;           // d-range half
    const int ty   = out >> 4;          // 0..7
    const int t    = out & 15;
    const int k    = k0 + ty;
    const int d0   = half * 128;

    float a0 = 0.f, a1 = 0.f, a2 = 0.f, a3 = 0.f;
    #pragma unroll 8
    for (int d = d0; d < d0 + 128; d += 4) {
        a0 += w_s[ty][d]     * q_s[t][d];
        a1 += w_s[ty][d + 1] * q_s[t][d + 1];
        a2 += w_s[ty][d + 2] * q_s[t][d + 2];
        a3 += w_s[ty][d + 3] * q_s[t][d + 3];
    }
    float part = (a0 + a1) + (a2 + a3);
    float acc  = part + __shfl_xor_sync(0xffffffffu, part, 1);

    if (half == 0) {
        acc *= WSCALE;
        __half hi = __float2half_rn(acc);
        __half lo = __float2half_rn(acc - __half2float(hi));
        const int ci = k >> 6, kin = k & 63;
        const uint32_t off = SWZ128((uint32_t)(t * 128 + kin * 2));
        *(unsigned short*)((char*)g_Ws16[0][ci] + off) = __half_as_ushort(hi);
        *(unsigned short*)((char*)g_Ws16[1][ci] + off) = __half_as_ushort(lo);
    }

    if (blk == 0 && tid < T_SZ) {
        float b0 = 0.f, b1 = 0.f, b2 = 0.f, b3 = 0.f;
        for (int d = 0; d < D_SZ; d += 4) {
            b0 += bp[d]     * q_s[tid][d];
            b1 += bp[d + 1] * q_s[tid][d + 1];
            b2 += bp[d + 2] * q_s[tid][d + 2];
            b3 += bp[d + 3] * q_s[tid][d + 3];
        }
        g_bs[tid] = ((b0 + b1) + (b2 + b3)) * (XSCALE * WSCALE);
    }
}

__global__ __launch_bounds__(256)
void prep_all_kernel(const float* __restrict__ Wp,
                     const float* __restrict__ bp,
                     const float* __restrict__ sigs_raw,
                     const float* __restrict__ Wc) {
    __shared__ __align__(16) char s_all[33024];
    const int b = blockIdx.x;
    if (b < 26)       prep_B_body(b, Wp, s_all);
    else if (b < 90)  prep_Wc_body(b - 26, Wc, s_all);
    else              prep_Ws_body(b - 90, Wp, bp, sigs_raw, s_all);
}

// ========================================================================
// Kernel 1: EXACT R10/R12 version (measured 82.1us). FROZEN.
// ========================================================================
#define NT1 512
#define SMEM1 139264
#define A_ST(st, sp) ((st) * 32768 + (sp) * 16384)
#define B_ST(st)     (65536 + (st) * 32768)
#define W_ST(st, sp) (131072 + (st) * 4096 + (sp) * 2048)

__global__ __launch_bounds__(NT1, 1)
void k1_proj_route(const float* __restrict__ x,
                   const float* __restrict__ bp,
                   float* __restrict__ out_idx,
                   int write_idx)
{
    extern __shared__ char sm[];
    __shared__ float bp_s[D_SZ];
    __shared__ float sb_s[T_SZ];
    __shared__ int s_cnt[T_SZ];
    __shared__ int s_base[T_SZ];

    const int tid  = threadIdx.x;
    const int lane = tid & 31;
    const int wid  = tid >> 5;
    const int wm   = wid >> 2;
    const int wn   = wid & 3;
    const int row0 = blockIdx.x * 128;

    const uint32_t smb = smem_u32(sm);

    if (tid < D_SZ) bp_s[tid] = bp[tid];
    if (tid < T_SZ) { s_cnt[tid] = 0; sb_s[tid] = g_bs[tid]; }

    auto ldgA = [&](int ci, int h, float4* xr) {
        #pragma unroll
        for (int i = 0; i < 2; i++) {
            const int e   = (h * 2 + i) * 512 + tid;
            const int row = e >> 4;
            const int q4  = e & 15;
            float4 v = make_float4(0.f, 0.f, 0.f, 0.f);
            if (ci < 12 || q4 < 4)
                v = *(const float4*)(x + (size_t)(row0 + row) * DIN_SZ + ci * 64 + q4 * 4);
            xr[i] = v;
        }
    };
    auto stsA = [&](int h, int st, const float4* xr) {
        #pragma unroll
        for (int i = 0; i < 2; i++) {
            const int e   = (h * 2 + i) * 512 + tid;
            const int row = e >> 4;
            const int q4  = e & 15;
            const float vx = xr[i].x * XSCALE, vy = xr[i].y * XSCALE;
            const float vz = xr[i].z * XSCALE, vw = xr[i].w * XSCALE;
            __half h0 = __float2half_rn(vx), h1 = __float2half_rn(vy);
            __half h2 = __float2half_rn(vz), h3 = __float2half_rn(vw);
            uint2 hv, lv;
            hv.x = ((uint32_t)__half_as_ushort(h1) << 16) | __half_as_ushort(h0);
            hv.y = ((uint32_t)__half_as_ushort(h3) << 16) | __half_as_ushort(h2);
            lv.x = pack_h2(vx - __half2float(h0), vy - __half2float(h1));
            lv.y = pack_h2(vz - __half2float(h2), vw - __half2float(h3));
            const uint32_t off = SWZ128((uint32_t)(row * 128 + q4 * 8));
            *(uint2*)(sm + A_ST(st, 0) + off) = hv;
            *(uint2*)(sm + A_ST(st, 1) + off) = lv;
        }
    };
    auto issueB = [&](int ci, int st) {
        #pragma unroll
        for (int i = 0; i < 4; i++) {
            const int g = tid + i * 512;
            CP_ASYNC16(smb + B_ST(st) + g * 16, (const void*)&g_B16[0][ci][g]);
        }
        if (tid < 256) {
            const int sp = tid >> 7, g = tid & 127;
            CP_ASYNC16(smb + W_ST(st, sp) + g * 16, (const void*)&g_Ws16[sp][ci][g]);
        }
        CP_COMMIT();
    };

    uint32_t a_off[2], b_off[4], sa_off, ws_off;
    #pragma unroll
    for (int mt = 0; mt < 2; mt++)
        a_off[mt] = (uint32_t)((wm * 32 + mt * 16 + (lane & 15)) * 128 + (lane >> 4) * 16);
    #pragma unroll
    for (int np = 0; np < 4; np++) {
        const int bn = wn * 64 + np * 16 + ((lane >> 4) << 3) + (lane & 7);
        b_off[np] = (uint32_t)(bn * 128 + ((lane >> 3) & 1) * 16);
    }
    sa_off = (uint32_t)((wid * 16 + (lane & 15)) * 128 + (lane >> 4) * 16);
    ws_off = (uint32_t)((((lane >> 4) << 3) + (lane & 7)) * 128 + ((lane >> 3) & 1) * 16);

    float acc[2][8][4];
    #pragma unroll
    for (int mt = 0; mt < 2; mt++)
        #pragma unroll
        for (int n8 = 0; n8 < 8; n8++)
            #pragma unroll
            for (int c = 0; c < 4; c++) acc[mt][n8][c] = 0.0f;
    float sacc[2][4];
    #pragma unroll
    for (int n8 = 0; n8 < 2; n8++)
        #pragma unroll
        for (int c = 0; c < 4; c++) sacc[n8][c] = 0.0f;

    issueB(0, 0);
    issueB(1, 1);
    {
        float4 xr[2];
        ldgA(0, 0, xr); stsA(0, 0, xr);
        ldgA(0, 1, xr); stsA(1, 0, xr);
    }
    CP_WAIT(1);
    __syncthreads();

    for (int ci = 0; ci < NCHUNK; ci++) {
        const int st = ci & 1;
        const bool nx = (ci + 1 < NCHUNK);
        const uint32_t a_hi = smb + A_ST(st, 0);
        const uint32_t a_lo = smb + A_ST(st, 1);
        const uint32_t b_hi = smb + B_ST(st);
        const uint32_t w_hi = smb + W_ST(st, 0);
        const uint32_t w_lo = smb + W_ST(st, 1);

        float4 xr[2];
        if (nx) ldgA(ci + 1, 0, xr);

        #pragma unroll
        for (int ks = 0; ks < 4; ks++) {
            uint32_t ah[2][4];
            #pragma unroll
            for (int mt = 0; mt < 2; mt++)
                ldsm4(ah[mt], a_hi + SWZ128(a_off[mt] + ks * 32));

            #pragma unroll
            for (int np = 0; np < 4; np++) {
                uint32_t r[4];
                ldsm4(r, b_hi + SWZ128(b_off[np] + ks * 32));
                #pragma unroll
                for (int mt = 0; mt < 2; mt++) {
                    mma16816(acc[mt][np * 2],     ah[mt], r);
                    mma16816(acc[mt][np * 2 + 1], ah[mt], r + 2);
                }
            }

            if (wid < 8) {
                uint32_t sah[4], sal[4];
                ldsm4(sah, a_hi + SWZ128(sa_off + ks * 32));
                ldsm4(sal, a_lo + SWZ128(sa_off + ks * 32));
                uint32_t wsh[2][2], wsl[2][2];
                {
                    uint32_t r[4];
                    ldsm4(r, w_hi + SWZ128(ws_off + ks * 32));
                    wsh[0][0] = r[0]; wsh[0][1] = r[1]; wsh[1][0] = r[2]; wsh[1][1] = r[3];
                    ldsm4(r, w_lo + SWZ128(ws_off + ks * 32));
                    wsl[0][0] = r[0]; wsl[0][1] = r[1]; wsl[1][0] = r[2]; wsl[1][1] = r[3];
                }
                #pragma unroll
                for (int n8 = 0; n8 < 2; n8++) {
                    mma16816(sacc[n8], sah, wsh[n8]);
                    mma16816(sacc[n8], sah, wsl[n8]);
                    mma16816(sacc[n8], sal, wsh[n8]);
                }
            }

            if (ks == 1 && nx) { stsA(0, st ^ 1, xr); ldgA(ci + 1, 1, xr); }
        }
        if (nx) stsA(1, st ^ 1, xr);

        __syncthreads();
        if (ci + 2 < NCHUNK) issueB(ci + 2, st);
        if (nx) { CP_WAIT(1); __syncthreads(); }
    }

    __syncthreads();

    uint32_t* hsm32 = (uint32_t*)sm;
    #pragma unroll
    for (int mt = 0; mt < 2; mt++) {
        const int r_a = wm * 32 + mt * 16 + (lane >> 2);
        #pragma unroll
        for (int n8 = 0; n8 < 8; n8++) {
            const int col = wn * 64 + n8 * 8 + (lane & 3) * 2;
            #pragma unroll
            for (int hf = 0; hf < 2; hf++) {
                const int rr = r_a + hf * 8;
                float a0 = (acc[mt][n8][hf * 2]     * INVSCALE + bp_s[col])     * XSCALE;
                float a1 = (acc[mt][n8][hf * 2 + 1] * INVSCALE + bp_s[col + 1]) * XSCALE;
                __half h0 = __float2half_rn(a0), h1 = __float2half_rn(a1);
                uint32_t hv = ((uint32_t)__half_as_ushort(h1) << 16) | __half_as_ushort(h0);
                uint32_t lv = pack_h2(a0 - __half2float(h0), a1 - __half2float(h1));
                hsm32[rr * 128 + (col >> 1)]         = hv;
                hsm32[16384 + rr * 128 + (col >> 1)] = lv;
            }
        }
    }

    int   my_bt[2];
    int   my_row[2];
    const bool writer = (wid < 8) && ((lane & 3) == 0);
    if (wid < 8) {
        const int c0 = (lane & 3) * 2;
        const float sb0 = sb_s[c0];
        const float sb1 = sb_s[c0 + 1];
        const float sb2 = sb_s[c0 + 8];
        const float sb3 = sb_s[c0 + 9];
        #pragma unroll
        for (int hf = 0; hf < 2; hf++) {
            float v0 = sacc[0][hf * 2]     + sb0;
            float v1 = sacc[0][hf * 2 + 1] + sb1;
            float v2 = sacc[1][hf * 2]     + sb2;
            float v3 = sacc[1][hf * 2 + 1] + sb3;
            float bv = v0; int bi = c0;
            if (v1 > bv) { bv = v1; bi = c0 + 1; }
            if (v2 > bv) { bv = v2; bi = c0 + 8; }
            if (v3 > bv) { bv = v3; bi = c0 + 9; }
            #pragma unroll
            for (int d = 1; d <= 2; d <<= 1) {
                float ov = __shfl_xor_sync(0xffffffffu, bv, d);
                int   oi = __shfl_xor_sync(0xffffffffu, bi, d);
                if (ov > bv || (ov == bv && oi < bi)) { bv = ov; bi = oi; }
            }
            my_bt[hf]  = bi;
            my_row[hf] = wid * 16 + hf * 8 + (lane >> 2);
        }
    }

    int lpos[2];
    if (writer) {
        #pragma unroll
        for (int q = 0; q < 2; q++)
            lpos[q] = atomicAdd(&s_cnt[my_bt[q]], 1);
    }
    __syncthreads();
    if (tid < T_SZ) s_base[tid] = atomicAdd(&g_counts[tid], s_cnt[tid]);
    __syncthreads();
    if (writer) {
        #pragma unroll
        for (int q = 0; q < 2; q++) {
            const int r = row0 + my_row[q];
            g_rowlist[my_bt[q] * B_SZ + s_base[my_bt[q]] + lpos[q]] = r;
            if (write_idx) out_idx[r] = (float)my_bt[q];
        }
    }

    #pragma unroll
    for (int sp = 0; sp < 2; sp++) {
        #pragma unroll
        for (int i = 0; i < 8; i++) {
            const int e   = tid + i * 512;
            const int row = e >> 5, q4 = e & 31;
            ((uint4*)&g_h16[sp][row0 + row][0])[q4] =
                ((const uint4*)&hsm32[sp * 16384])[e];
        }
    }
}

// ========================================================================
// Kernel 2: HMMA routed classifier, 3-product (R12 exact, measured-correct)
// ========================================================================
#define BM2 128
#define NT2 256
#define K2CH 4
#define A2_ST(st, sp) ((st) * 32768 + (sp) * 16384)
#define W2_ST(st, sp) (65536 + (st) * 16384 + (sp) * 8192)
#define SMEM2 98304

__global__ __launch_bounds__(NT2, 2)
void k2_classifier(const float* __restrict__ bc,
                   float* __restrict__ out)
{
    extern __shared__ char sm2[];
    __shared__ int rid_s[BM2];

    const int t    = blockIdx.y;
    const int cnt  = g_counts[t];
    const int base = blockIdx.x * BM2;
    if (base >= cnt) return;
    const int n = min(BM2, cnt - base);

    const int tid  = threadIdx.x;
    const int lane = tid & 31;
    const int wid  = tid >> 5;
    const int wm2  = wid >> 1;
    const int wn2  = wid & 1;
    const uint32_t smb = smem_u32(sm2);

    if (tid < BM2) {
        int idx = (tid < n) ? tid : (n - 1);
        rid_s[tid] = g_rowlist[t * B_SZ + base + idx];
    }
    __syncthreads();

    auto issue2 = [&](int ci, int st) {
        #pragma unroll
        for (int i = 0; i < 8; i++) {
            const int e   = tid + i * 256;
            const int sp  = e >> 10;
            const int rem = e & 1023;
            const int row = rem >> 3, q = rem & 7;
            const uint32_t dst = smb + A2_ST(st, sp) + SWZ128((uint32_t)(row * 128 + q * 16));
            CP_ASYNC16(dst, (const void*)&g_h16[sp][rid_s[row]][ci * 32 + q * 4]);
        }
        #pragma unroll
        for (int i = 0; i < 4; i++) {
            const int e  = tid + i * 256;
            const int sp = e >> 9, g = e & 511;
            CP_ASYNC16(smb + W2_ST(st, sp) + g * 16, (const void*)&g_Wc16[sp][t][ci][g]);
        }
        CP_COMMIT();
    };

    uint32_t a_off[2], b_off[2];
    #pragma unroll
    for (int mt = 0; mt < 2; mt++)
        a_off[mt] = (uint32_t)((wm2 * 32 + mt * 16 + (lane & 15)) * 128 + (lane >> 4) * 16);
    #pragma unroll
    for (int np = 0; np < 2; np++) {
        const int bn = wn2 * 32 + np * 16 + ((lane >> 4) << 3) + (lane & 7);
        b_off[np] = (uint32_t)(bn * 128 + ((lane >> 3) & 1) * 16);
    }

    float acc[2][4][4];
    #pragma unroll
    for (int mt = 0; mt < 2; mt++)
        #pragma unroll
        for (int n8 = 0; n8 < 4; n8++)
            #pragma unroll
            for (int c = 0; c < 4; c++) acc[mt][n8][c] = 0.0f;

    issue2(0, 0);
    issue2(1, 1);
    CP_WAIT(1);
    __syncthreads();

    for (int ci = 0; ci < K2CH; ci++) {
        const int st = ci & 1;
        const uint32_t a_hi = smb + A2_ST(st, 0);
        const uint32_t a_lo = smb + A2_ST(st, 1);
        const uint32_t w_hi = smb + W2_ST(st, 0);
        const uint32_t w_lo = smb + W2_ST(st, 1);

        #pragma unroll
        for (int ks = 0; ks < 4; ks++) {
            uint32_t ah[2][4], al[2][4];
            #pragma unroll
            for (int mt = 0; mt < 2; mt++) {
                ldsm4(ah[mt], a_hi + SWZ128(a_off[mt] + ks * 32));
                ldsm4(al[mt], a_lo + SWZ128(a_off[mt] + ks * 32));
            }
            uint32_t bh[4][2], bl[4][2];
            #pragma unroll
            for (int np = 0; np < 2; np++) {
                uint32_t r[4];
                ldsm4(r, w_hi + SWZ128(b_off[np] + ks * 32));
                bh[np * 2][0] = r[0]; bh[np * 2][1] = r[1];
                bh[np * 2 + 1][0] = r[2]; bh[np * 2 + 1][1] = r[3];
                ldsm4(r, w_lo + SWZ128(b_off[np] + ks * 32));
                bl[np * 2][0] = r[0]; bl[np * 2][1] = r[1];
                bl[np * 2 + 1][0] = r[2]; bl[np * 2 + 1][1] = r[3];
            }
            #pragma unroll
            for (int mt = 0; mt < 2; mt++)
                #pragma unroll
                for (int n8 = 0; n8 < 4; n8++) {
                    mma16816(acc[mt][n8], ah[mt], bh[n8]);
                    mma16816(acc[mt][n8], ah[mt], bl[n8]);
                    mma16816(acc[mt][n8], al[mt], bh[n8]);
                }
        }
        __syncthreads();
        if (ci + 2 < K2CH) issue2(ci + 2, st);
        if (ci + 1 < K2CH) { CP_WAIT(1); __syncthreads(); }
    }

    #pragma unroll
    for (int mt = 0; mt < 2; mt++) {
        const int r_a = wm2 * 32 + mt * 16 + (lane >> 2);
        #pragma unroll
        for (int n8 = 0; n8 < 4; n8++) {
            const int col = wn2 * 32 + n8 * 8 + (lane & 3) * 2;
            const float b0 = bc[t * C_SZ + col];
            const float b1 = bc[t * C_SZ + col + 1];
            #pragma unroll
            for (int hf = 0; hf < 2; hf++) {
                const int lr = r_a + hf * 8;
                if (lr < n) {
                    float2 v;
                    v.x = acc[mt][n8][hf * 2]     * INVSCALE + b0;
                    v.y = acc[mt][n8][hf * 2 + 1] * INVSCALE + b1;
                    *(float2*)(out + (size_t)rid_s[lr] * C_SZ + col) = v;
                }
            }
        }
    }
}

// ========================================================================
extern "C" void kernel_launch(void* const* d_in, const int* in_sizes, int n_in,
                              void* d_out, int out_size)
{
    const float* x    = (const float*)d_in[0];
    const float* Wp   = (const float*)d_in[1];
    const float* bp   = (const float*)d_in[2];
    const float* sigs = (const float*)d_in[3];
    const float* Wc   = (const float*)d_in[4];
    const float* bc   = (const float*)d_in[5];
    float* out = (float*)d_out;

    const int write_idx = (out_size >= B_SZ * C_SZ + B_SZ) ? 1 : 0;
    (void)in_sizes; (void)n_in;

    prep_all_kernel<<<194, 256>>>(Wp, bp, sigs, Wc);

    cudaFuncSetAttribute(k1_proj_route, cudaFuncAttributeMaxDynamicSharedMemorySize, SMEM1);
    k1_proj_route<<<NBLK, NT1, SMEM1>>>(x, bp, out + B_SZ * C_SZ, write_idx);

    cudaFuncSetAttribute(k2_classifier, cudaFuncAttributeMaxDynamicSharedMemorySize, SMEM2);
    dim3 g2(B_SZ / BM2, T_SZ);
    k2_classifier<<<g2, NT2, SMEM2>>>(bc, out);
}

// round 15
// speedup vs baseline: 1.2684x; 1.0684x over previous
#include <cuda_runtime.h>
#include <cuda_fp16.h>
#include <cstdint>

#define B_SZ 32768
#define DIN_SZ 784
#define D_SZ 256
#define T_SZ 16
#define C_SZ 64
#define NCHUNK 13            // K padded to 832, BK=64
#define NBLK (B_SZ / 128)

// ---------------- scratch (static __device__, no allocs) ----------------
__device__ uint32_t g_h16[2][B_SZ][128];     // h hi/lo fp16 pairs (x16 scaled)
__device__ int   g_rowlist[T_SZ * B_SZ];
__device__ int   g_counts[T_SZ];
__device__ uint4 g_B16[2][NCHUNK][2048];     // Wp^T hi/lo fp16 swizzled
__device__ uint4 g_Ws16[2][NCHUNK][128];     // Ws^T hi/lo fp16 swizzled
__device__ uint4 g_Wc16[2][T_SZ][4][512];    // Wc^T hi/lo fp16 swizzled per tile/chunk
__device__ float g_bs[T_SZ];                 // 1024 * (bp @ q(sigs)^T)

#define XSCALE 16.0f
#define WSCALE 64.0f
#define INVSCALE (1.0f / 1024.0f)

// ---------------- helpers ----------------
__device__ __forceinline__ uint32_t smem_u32(const void* p) {
    uint32_t a;
    asm("{ .reg .u64 t; cvta.to.shared.u64 t, %1; cvt.u32.u64 %0, t; }" : "=r"(a) : "l"(p));
    return a;
}
#define SWZ128(o) ((o) ^ (((o) >> 3) & 0x70))

#define CP_ASYNC16(dst, src) \
    asm volatile("cp.async.cg.shared.global [%0], [%1], 16;" :: "r"(dst), "l"(src))
#define CP_COMMIT() asm volatile("cp.async.commit_group;" ::: "memory")
#define CP_WAIT(n)  asm volatile("cp.async.wait_group %0;" :: "n"(n) : "memory")

__device__ __forceinline__ void ldsm4(uint32_t* r, uint32_t addr) {
    asm volatile("ldmatrix.sync.aligned.m8n8.x4.shared.b16 {%0,%1,%2,%3}, [%4];"
                 : "=r"(r[0]), "=r"(r[1]), "=r"(r[2]), "=r"(r[3]) : "r"(addr));
}
__device__ __forceinline__ void mma16816(float* c, const uint32_t* a, const uint32_t* b) {
    asm volatile("mma.sync.aligned.m16n8k16.row.col.f32.f16.f16.f32 "
                 "{%0,%1,%2,%3}, {%4,%5,%6,%7}, {%8,%9}, {%0,%1,%2,%3};"
                 : "+f"(c[0]), "+f"(c[1]), "+f"(c[2]), "+f"(c[3])
                 : "r"(a[0]), "r"(a[1]), "r"(a[2]), "r"(a[3]), "r"(b[0]), "r"(b[1]));
}
__device__ __forceinline__ uint32_t pack_h2(float a, float b) {
    __half h0 = __float2half_rn(a), h1 = __float2half_rn(b);
    return ((uint32_t)__half_as_ushort(h1) << 16) | __half_as_ushort(h0);
}

// ========================================================================
// Fused prep kernel (R14 exact, measured 20.3us):
// [0,26) prep_B; [26,90) prep_Wc; [90,194) prep_Ws (8 k-rows, 2 thr/out).
// ========================================================================
__device__ void prep_B_body(int blk, const float* __restrict__ Wp, char* s_all) {
    float (*ws_s)[256] = (float(*)[256])s_all;
    const int ci   = blk >> 1;
    const int half = blk & 1;
    const int tid  = threadIdx.x;
    const int kbase = ci * 64 + half * 32;

    for (int e = tid; e < 2048; e += 256) {
        const int r = e >> 6, c4 = e & 63;
        const int k = kbase + r;
        float4 v = make_float4(0.f, 0.f, 0.f, 0.f);
        if (k < DIN_SZ) v = ((const float4*)(Wp + (size_t)k * D_SZ))[c4];
        *(float4*)&ws_s[r][c4 * 4] = v;
    }
    __syncthreads();

    #pragma unroll
    for (int i = 0; i < 4; i++) {
        const int e  = tid + i * 256;
        const int n  = e & 255;
        const int kq = e >> 8;
        float v[8], h[8];
        #pragma unroll
        for (int j = 0; j < 8; j++) {
            v[j] = ws_s[kq * 8 + j][n] * WSCALE;
            h[j] = __half2float(__float2half_rn(v[j]));
        }
        uint4 hi, lo;
        hi.x = pack_h2(v[0], v[1]); hi.y = pack_h2(v[2], v[3]);
        hi.z = pack_h2(v[4], v[5]); hi.w = pack_h2(v[6], v[7]);
        lo.x = pack_h2(v[0] - h[0], v[1] - h[1]); lo.y = pack_h2(v[2] - h[2], v[3] - h[3]);
        lo.z = pack_h2(v[4] - h[4], v[5] - h[5]); lo.w = pack_h2(v[6] - h[6], v[7] - h[7]);
        const uint32_t off = SWZ128((uint32_t)(n * 128 + (half * 4 + kq) * 16));
        g_B16[0][ci][off >> 4] = hi;
        g_B16[1][ci][off >> 4] = lo;
    }
}

__device__ void prep_Wc_body(int blk, const float* __restrict__ Wc, char* s_all) {
    float (*wc_s)[64] = (float(*)[64])s_all;
    const int t   = blk >> 2;
    const int ci  = blk & 3;
    const int tid = threadIdx.x;

    #pragma unroll
    for (int i = 0; i < 4; i++) {
        const int e = tid + i * 256;
        const int r = e >> 4, c4 = e & 15;
        *(float4*)&wc_s[r][c4 * 4] =
            ((const float4*)(Wc + ((size_t)t * 256 + ci * 64 + r) * C_SZ))[c4];
    }
    __syncthreads();

    #pragma unroll
    for (int i = 0; i < 2; i++) {
        const int e = tid + i * 256;
        const int n = e >> 3, q = e & 7;
        float v[8], h[8];
        #pragma unroll
        for (int j = 0; j < 8; j++) {
            v[j] = wc_s[q * 8 + j][n] * WSCALE;
            h[j] = __half2float(__float2half_rn(v[j]));
        }
        uint4 hi, lo;
        hi.x = pack_h2(v[0], v[1]); hi.y = pack_h2(v[2], v[3]);
        hi.z = pack_h2(v[4], v[5]); hi.w = pack_h2(v[6], v[7]);
        lo.x = pack_h2(v[0] - h[0], v[1] - h[1]); lo.y = pack_h2(v[2] - h[2], v[3] - h[3]);
        lo.z = pack_h2(v[4] - h[4], v[5] - h[5]); lo.w = pack_h2(v[6] - h[6], v[7] - h[7]);
        const uint32_t off = SWZ128((uint32_t)(n * 128 + q * 16));
        g_Wc16[0][t][ci][off >> 4] = hi;
        g_Wc16[1][t][ci][off >> 4] = lo;
    }
}

__device__ void prep_Ws_body(int blk, const float* __restrict__ Wp,
                             const float* __restrict__ bp,
                             const float* __restrict__ sigs_raw, char* s_all) {
    float (*q_s)[257] = (float(*)[257])s_all;
    float (*w_s)[257] = (float(*)[257])(s_all + 16 * 257 * 4);
    const int tid = threadIdx.x;
    const int k0  = blk * 8;

    if (blk == 0 && tid < T_SZ) g_counts[tid] = 0;

    for (int e = tid; e < T_SZ * D_SZ; e += 256) {
        const int t = e >> 8, d = e & 255;
        float s = sigs_raw[e];
        q_s[t][d] = (s > 0.3f) ? 1.0f : ((s < -0.3f) ? -1.0f : 0.0f);
    }
    for (int e = tid; e < 8 * D_SZ; e += 256) {
        const int r = e >> 8, d = e & 255;
        const int k = k0 + r;
        w_s[r][d] = (k < DIN_SZ) ? Wp[(size_t)k * D_SZ + d] : 0.f;
    }
    __syncthreads();

    const int out  = tid >> 1;
    const int half = tid & 1;
    const int ty   = out >> 4;
    const int t    = out & 15;
    const int k    = k0 + ty;
    const int d0   = half * 128;

    float a0 = 0.f, a1 = 0.f, a2 = 0.f, a3 = 0.f;
    #pragma unroll 8
    for (int d = d0; d < d0 + 128; d += 4) {
        a0 += w_s[ty][d]     * q_s[t][d];
        a1 += w_s[ty][d + 1] * q_s[t][d + 1];
        a2 += w_s[ty][d + 2] * q_s[t][d + 2];
        a3 += w_s[ty][d + 3] * q_s[t][d + 3];
    }
    float part = (a0 + a1) + (a2 + a3);
    float acc  = part + __shfl_xor_sync(0xffffffffu, part, 1);

    if (half == 0) {
        acc *= WSCALE;
        __half hi = __float2half_rn(acc);
        __half lo = __float2half_rn(acc - __half2float(hi));
        const int ci = k >> 6, kin = k & 63;
        const uint32_t off = SWZ128((uint32_t)(t * 128 + kin * 2));
        *(unsigned short*)((char*)g_Ws16[0][ci] + off) = __half_as_ushort(hi);
        *(unsigned short*)((char*)g_Ws16[1][ci] + off) = __half_as_ushort(lo);
    }

    if (blk == 0 && tid < T_SZ) {
        float b0 = 0.f, b1 = 0.f, b2 = 0.f, b3 = 0.f;
        for (int d = 0; d < D_SZ; d += 4) {
            b0 += bp[d]     * q_s[tid][d];
            b1 += bp[d + 1] * q_s[tid][d + 1];
            b2 += bp[d + 2] * q_s[tid][d + 2];
            b3 += bp[d + 3] * q_s[tid][d + 3];
        }
        g_bs[tid] = ((b0 + b1) + (b2 + b3)) * (XSCALE * WSCALE);
    }
}

__global__ __launch_bounds__(256)
void prep_all_kernel(const float* __restrict__ Wp,
                     const float* __restrict__ bp,
                     const float* __restrict__ sigs_raw,
                     const float* __restrict__ Wc) {
    __shared__ __align__(16) char s_all[33024];
    const int b = blockIdx.x;
    if (b < 26)       prep_B_body(b, Wp, s_all);
    else if (b < 90)  prep_Wc_body(b - 26, Wc, s_all);
    else              prep_Ws_body(b - 90, Wp, bp, sigs_raw, s_all);
}

// ========================================================================
// Kernel 1: EXACT R10/R12/R14 version (measured 82.1us). FROZEN.
// ========================================================================
#define NT1 512
#define SMEM1 139264
#define A_ST(st, sp) ((st) * 32768 + (sp) * 16384)
#define B_ST(st)     (65536 + (st) * 32768)
#define W_ST(st, sp) (131072 + (st) * 4096 + (sp) * 2048)

__global__ __launch_bounds__(NT1, 1)
void k1_proj_route(const float* __restrict__ x,
                   const float* __restrict__ bp,
                   float* __restrict__ out_idx,
                   int write_idx)
{
    extern __shared__ char sm[];
    __shared__ float bp_s[D_SZ];
    __shared__ float sb_s[T_SZ];
    __shared__ int s_cnt[T_SZ];
    __shared__ int s_base[T_SZ];

    const int tid  = threadIdx.x;
    const int lane = tid & 31;
    const int wid  = tid >> 5;
    const int wm   = wid >> 2;
    const int wn   = wid & 3;
    const int row0 = blockIdx.x * 128;

    const uint32_t smb = smem_u32(sm);

    if (tid < D_SZ) bp_s[tid] = bp[tid];
    if (tid < T_SZ) { s_cnt[tid] = 0; sb_s[tid] = g_bs[tid]; }

    auto ldgA = [&](int ci, int h, float4* xr) {
        #pragma unroll
        for (int i = 0; i < 2; i++) {
            const int e   = (h * 2 + i) * 512 + tid;
            const int row = e >> 4;
            const int q4  = e & 15;
            float4 v = make_float4(0.f, 0.f, 0.f, 0.f);
            if (ci < 12 || q4 < 4)
                v = *(const float4*)(x + (size_t)(row0 + row) * DIN_SZ + ci * 64 + q4 * 4);
            xr[i] = v;
        }
    };
    auto stsA = [&](int h, int st, const float4* xr) {
        #pragma unroll
        for (int i = 0; i < 2; i++) {
            const int e   = (h * 2 + i) * 512 + tid;
            const int row = e >> 4;
            const int q4  = e & 15;
            const float vx = xr[i].x * XSCALE, vy = xr[i].y * XSCALE;
            const float vz = xr[i].z * XSCALE, vw = xr[i].w * XSCALE;
            __half h0 = __float2half_rn(vx), h1 = __float2half_rn(vy);
            __half h2 = __float2half_rn(vz), h3 = __float2half_rn(vw);
            uint2 hv, lv;
            hv.x = ((uint32_t)__half_as_ushort(h1) << 16) | __half_as_ushort(h0);
            hv.y = ((uint32_t)__half_as_ushort(h3) << 16) | __half_as_ushort(h2);
            lv.x = pack_h2(vx - __half2float(h0), vy - __half2float(h1));
            lv.y = pack_h2(vz - __half2float(h2), vw - __half2float(h3));
            const uint32_t off = SWZ128((uint32_t)(row * 128 + q4 * 8));
            *(uint2*)(sm + A_ST(st, 0) + off) = hv;
            *(uint2*)(sm + A_ST(st, 1) + off) = lv;
        }
    };
    auto issueB = [&](int ci, int st) {
        #pragma unroll
        for (int i = 0; i < 4; i++) {
            const int g = tid + i * 512;
            CP_ASYNC16(smb + B_ST(st) + g * 16, (const void*)&g_B16[0][ci][g]);
        }
        if (tid < 256) {
            const int sp = tid >> 7, g = tid & 127;
            CP_ASYNC16(smb + W_ST(st, sp) + g * 16, (const void*)&g_Ws16[sp][ci][g]);
        }
        CP_COMMIT();
    };

    uint32_t a_off[2], b_off[4], sa_off, ws_off;
    #pragma unroll
    for (int mt = 0; mt < 2; mt++)
        a_off[mt] = (uint32_t)((wm * 32 + mt * 16 + (lane & 15)) * 128 + (lane >> 4) * 16);
    #pragma unroll
    for (int np = 0; np < 4; np++) {
        const int bn = wn * 64 + np * 16 + ((lane >> 4) << 3) + (lane & 7);
        b_off[np] = (uint32_t)(bn * 128 + ((lane >> 3) & 1) * 16);
    }
    sa_off = (uint32_t)((wid * 16 + (lane & 15)) * 128 + (lane >> 4) * 16);
    ws_off = (uint32_t)((((lane >> 4) << 3) + (lane & 7)) * 128 + ((lane >> 3) & 1) * 16);

    float acc[2][8][4];
    #pragma unroll
    for (int mt = 0; mt < 2; mt++)
        #pragma unroll
        for (int n8 = 0; n8 < 8; n8++)
            #pragma unroll
            for (int c = 0; c < 4; c++) acc[mt][n8][c] = 0.0f;
    float sacc[2][4];
    #pragma unroll
    for (int n8 = 0; n8 < 2; n8++)
        #pragma unroll
        for (int c = 0; c < 4; c++) sacc[n8][c] = 0.0f;

    issueB(0, 0);
    issueB(1, 1);
    {
        float4 xr[2];
        ldgA(0, 0, xr); stsA(0, 0, xr);
        ldgA(0, 1, xr); stsA(1, 0, xr);
    }
    CP_WAIT(1);
    __syncthreads();

    for (int ci = 0; ci < NCHUNK; ci++) {
        const int st = ci & 1;
        const bool nx = (ci + 1 < NCHUNK);
        const uint32_t a_hi = smb + A_ST(st, 0);
        const uint32_t a_lo = smb + A_ST(st, 1);
        const uint32_t b_hi = smb + B_ST(st);
        const uint32_t w_hi = smb + W_ST(st, 0);
        const uint32_t w_lo = smb + W_ST(st, 1);

        float4 xr[2];
        if (nx) ldgA(ci + 1, 0, xr);

        #pragma unroll
        for (int ks = 0; ks < 4; ks++) {
            uint32_t ah[2][4];
            #pragma unroll
            for (int mt = 0; mt < 2; mt++)
                ldsm4(ah[mt], a_hi + SWZ128(a_off[mt] + ks * 32));

            #pragma unroll
            for (int np = 0; np < 4; np++) {
                uint32_t r[4];
                ldsm4(r, b_hi + SWZ128(b_off[np] + ks * 32));
                #pragma unroll
                for (int mt = 0; mt < 2; mt++) {
                    mma16816(acc[mt][np * 2],     ah[mt], r);
                    mma16816(acc[mt][np * 2 + 1], ah[mt], r + 2);
                }
            }

            if (wid < 8) {
                uint32_t sah[4], sal[4];
                ldsm4(sah, a_hi + SWZ128(sa_off + ks * 32));
                ldsm4(sal, a_lo + SWZ128(sa_off + ks * 32));
                uint32_t wsh[2][2], wsl[2][2];
                {
                    uint32_t r[4];
                    ldsm4(r, w_hi + SWZ128(ws_off + ks * 32));
                    wsh[0][0] = r[0]; wsh[0][1] = r[1]; wsh[1][0] = r[2]; wsh[1][1] = r[3];
                    ldsm4(r, w_lo + SWZ128(ws_off + ks * 32));
                    wsl[0][0] = r[0]; wsl[0][1] = r[1]; wsl[1][0] = r[2]; wsl[1][1] = r[3];
                }
                #pragma unroll
                for (int n8 = 0; n8 < 2; n8++) {
                    mma16816(sacc[n8], sah, wsh[n8]);
                    mma16816(sacc[n8], sah, wsl[n8]);
                    mma16816(sacc[n8], sal, wsh[n8]);
                }
            }

            if (ks == 1 && nx) { stsA(0, st ^ 1, xr); ldgA(ci + 1, 1, xr); }
        }
        if (nx) stsA(1, st ^ 1, xr);

        __syncthreads();
        if (ci + 2 < NCHUNK) issueB(ci + 2, st);
        if (nx) { CP_WAIT(1); __syncthreads(); }
    }

    __syncthreads();

    uint32_t* hsm32 = (uint32_t*)sm;
    #pragma unroll
    for (int mt = 0; mt < 2; mt++) {
        const int r_a = wm * 32 + mt * 16 + (lane >> 2);
        #pragma unroll
        for (int n8 = 0; n8 < 8; n8++) {
            const int col = wn * 64 + n8 * 8 + (lane & 3) * 2;
            #pragma unroll
            for (int hf = 0; hf < 2; hf++) {
                const int rr = r_a + hf * 8;
                float a0 = (acc[mt][n8][hf * 2]     * INVSCALE + bp_s[col])     * XSCALE;
                float a1 = (acc[mt][n8][hf * 2 + 1] * INVSCALE + bp_s[col + 1]) * XSCALE;
                __half h0 = __float2half_rn(a0), h1 = __float2half_rn(a1);
                uint32_t hv = ((uint32_t)__half_as_ushort(h1) << 16) | __half_as_ushort(h0);
                uint32_t lv = pack_h2(a0 - __half2float(h0), a1 - __half2float(h1));
                hsm32[rr * 128 + (col >> 1)]         = hv;
                hsm32[16384 + rr * 128 + (col >> 1)] = lv;
            }
        }
    }

    int   my_bt[2];
    int   my_row[2];
    const bool writer = (wid < 8) && ((lane & 3) == 0);
    if (wid < 8) {
        const int c0 = (lane & 3) * 2;
        const float sb0 = sb_s[c0];
        const float sb1 = sb_s[c0 + 1];
        const float sb2 = sb_s[c0 + 8];
        const float sb3 = sb_s[c0 + 9];
        #pragma unroll
        for (int hf = 0; hf < 2; hf++) {
            float v0 = sacc[0][hf * 2]     + sb0;
            float v1 = sacc[0][hf * 2 + 1] + sb1;
            float v2 = sacc[1][hf * 2]     + sb2;
            float v3 = sacc[1][hf * 2 + 1] + sb3;
            float bv = v0; int bi = c0;
            if (v1 > bv) { bv = v1; bi = c0 + 1; }
            if (v2 > bv) { bv = v2; bi = c0 + 8; }
            if (v3 > bv) { bv = v3; bi = c0 + 9; }
            #pragma unroll
            for (int d = 1; d <= 2; d <<= 1) {
                float ov = __shfl_xor_sync(0xffffffffu, bv, d);
                int   oi = __shfl_xor_sync(0xffffffffu, bi, d);
                if (ov > bv || (ov == bv && oi < bi)) { bv = ov; bi = oi; }
            }
            my_bt[hf]  = bi;
            my_row[hf] = wid * 16 + hf * 8 + (lane >> 2);
        }
    }

    int lpos[2];
    if (writer) {
        #pragma unroll
        for (int q = 0; q < 2; q++)
            lpos[q] = atomicAdd(&s_cnt[my_bt[q]], 1);
    }
    __syncthreads();
    if (tid < T_SZ) s_base[tid] = atomicAdd(&g_counts[tid], s_cnt[tid]);
    __syncthreads();
    if (writer) {
        #pragma unroll
        for (int q = 0; q < 2; q++) {
            const int r = row0 + my_row[q];
            g_rowlist[my_bt[q] * B_SZ + s_base[my_bt[q]] + lpos[q]] = r;
            if (write_idx) out_idx[r] = (float)my_bt[q];
        }
    }

    #pragma unroll
    for (int sp = 0; sp < 2; sp++) {
        #pragma unroll
        for (int i = 0; i < 8; i++) {
            const int e   = tid + i * 512;
            const int row = e >> 5, q4 = e & 31;
            ((uint4*)&g_h16[sp][row0 + row][0])[q4] =
                ((const uint4*)&hsm32[sp * 16384])[e];
        }
    }
}

// ========================================================================
// Kernel 2: HMMA routed classifier, 3-product (R14 numerics). FLAT GRID:
// 272 CTAs; each maps itself to (tile, base) via register prefix walk.
// ========================================================================
#define BM2 128
#define NT2 256
#define K2CH 4
#define K2GRID 272
#define A2_ST(st, sp) ((st) * 32768 + (sp) * 16384)
#define W2_ST(st, sp) (65536 + (st) * 16384 + (sp) * 8192)
#define SMEM2 98304

__global__ __launch_bounds__(NT2, 2)
void k2_classifier(const float* __restrict__ bc,
                   float* __restrict__ out)
{
    extern __shared__ char sm2[];
    __shared__ int rid_s[BM2];

    // ---- flat block -> (tile, base) mapping (parallel count preload) ----
    int cnts[T_SZ];
    #pragma unroll
    for (int tt = 0; tt < T_SZ; tt++) cnts[tt] = g_counts[tt];

    const int i = blockIdx.x;
    int t = -1, base = 0, accb = 0;
    #pragma unroll
    for (int tt = 0; tt < T_SZ; tt++) {
        const int nb = (cnts[tt] + BM2 - 1) >> 7;
        if (t < 0 && i < accb + nb) { t = tt; base = (i - accb) * BM2; }
        accb += nb;
    }
    if (t < 0) return;
    const int cnt = cnts[t];
    const int n = min(BM2, cnt - base);

    const int tid  = threadIdx.x;
    const int lane = tid & 31;
    const int wid  = tid >> 5;
    const int wm2  = wid >> 1;
    const int wn2  = wid & 1;
    const uint32_t smb = smem_u32(sm2);

    if (tid < BM2) {
        int idx = (tid < n) ? tid : (n - 1);
        rid_s[tid] = g_rowlist[t * B_SZ + base + idx];
    }
    __syncthreads();

    auto issue2 = [&](int ci, int st) {
        #pragma unroll
        for (int i2 = 0; i2 < 8; i2++) {
            const int e   = tid + i2 * 256;
            const int sp  = e >> 10;
            const int rem = e & 1023;
            const int row = rem >> 3, q = rem & 7;
            const uint32_t dst = smb + A2_ST(st, sp) + SWZ128((uint32_t)(row * 128 + q * 16));
            CP_ASYNC16(dst, (const void*)&g_h16[sp][rid_s[row]][ci * 32 + q * 4]);
        }
        #pragma unroll
        for (int i2 = 0; i2 < 4; i2++) {
            const int e  = tid + i2 * 256;
            const int sp = e >> 9, g = e & 511;
            CP_ASYNC16(smb + W2_ST(st, sp) + g * 16, (const void*)&g_Wc16[sp][t][ci][g]);
        }
        CP_COMMIT();
    };

    uint32_t a_off[2], b_off[2];
    #pragma unroll
    for (int mt = 0; mt < 2; mt++)
        a_off[mt] = (uint32_t)((wm2 * 32 + mt * 16 + (lane & 15)) * 128 + (lane >> 4) * 16);
    #pragma unroll
    for (int np = 0; np < 2; np++) {
        const int bn = wn2 * 32 + np * 16 + ((lane >> 4) << 3) + (lane & 7);
        b_off[np] = (uint32_t)(bn * 128 + ((lane >> 3) & 1) * 16);
    }

    float acc[2][4][4];
    #pragma unroll
    for (int mt = 0; mt < 2; mt++)
        #pragma unroll
        for (int n8 = 0; n8 < 4; n8++)
            #pragma unroll
            for (int c = 0; c < 4; c++) acc[mt][n8][c] = 0.0f;

    issue2(0, 0);
    issue2(1, 1);
    CP_WAIT(1);
    __syncthreads();

    for (int ci = 0; ci < K2CH; ci++) {
        const int st = ci & 1;
        const uint32_t a_hi = smb + A2_ST(st, 0);
        const uint32_t a_lo = smb + A2_ST(st, 1);
        const uint32_t w_hi = smb + W2_ST(st, 0);
        const uint32_t w_lo = smb + W2_ST(st, 1);

        #pragma unroll
        for (int ks = 0; ks < 4; ks++) {
            uint32_t ah[2][4], al[2][4];
            #pragma unroll
            for (int mt = 0; mt < 2; mt++) {
                ldsm4(ah[mt], a_hi + SWZ128(a_off[mt] + ks * 32));
                ldsm4(al[mt], a_lo + SWZ128(a_off[mt] + ks * 32));
            }
            uint32_t bh[4][2], bl[4][2];
            #pragma unroll
            for (int np = 0; np < 2; np++) {
                uint32_t r[4];
                ldsm4(r, w_hi + SWZ128(b_off[np] + ks * 32));
                bh[np * 2][0] = r[0]; bh[np * 2][1] = r[1];
                bh[np * 2 + 1][0] = r[2]; bh[np * 2 + 1][1] = r[3];
                ldsm4(r, w_lo + SWZ128(b_off[np] + ks * 32));
                bl[np * 2][0] = r[0]; bl[np * 2][1] = r[1];
                bl[np * 2 + 1][0] = r[2]; bl[np * 2 + 1][1] = r[3];
            }
            #pragma unroll
            for (int mt = 0; mt < 2; mt++)
                #pragma unroll
                for (int n8 = 0; n8 < 4; n8++) {
                    mma16816(acc[mt][n8], ah[mt], bh[n8]);
                    mma16816(acc[mt][n8], ah[mt], bl[n8]);
                    mma16816(acc[mt][n8], al[mt], bh[n8]);
                }
        }
        __syncthreads();
        if (ci + 2 < K2CH) issue2(ci + 2, st);
        if (ci + 1 < K2CH) { CP_WAIT(1); __syncthreads(); }
    }

    #pragma unroll
    for (int mt = 0; mt < 2; mt++) {
        const int r_a = wm2 * 32 + mt * 16 + (lane >> 2);
        #pragma unroll
        for (int n8 = 0; n8 < 4; n8++) {
            const int col = wn2 * 32 + n8 * 8 + (lane & 3) * 2;
            const float b0 = bc[t * C_SZ + col];
            const float b1 = bc[t * C_SZ + col + 1];
            #pragma unroll
            for (int hf = 0; hf < 2; hf++) {
                const int lr = r_a + hf * 8;
                if (lr < n) {
                    float2 v;
                    v.x = acc[mt][n8][hf * 2]     * INVSCALE + b0;
                    v.y = acc[mt][n8][hf * 2 + 1] * INVSCALE + b1;
                    *(float2*)(out + (size_t)rid_s[lr] * C_SZ + col) = v;
                }
            }
        }
    }
}

// ========================================================================
extern "C" void kernel_launch(void* const* d_in, const int* in_sizes, int n_in,
                              void* d_out, int out_size)
{
    const float* x    = (const float*)d_in[0];
    const float* Wp   = (const float*)d_in[1];
    const float* bp   = (const float*)d_in[2];
    const float* sigs = (const float*)d_in[3];
    const float* Wc   = (const float*)d_in[4];
    const float* bc   = (const float*)d_in[5];
    float* out = (float*)d_out;

    const int write_idx = (out_size >= B_SZ * C_SZ + B_SZ) ? 1 : 0;
    (void)in_sizes; (void)n_in;

    prep_all_kernel<<<194, 256>>>(Wp, bp, sigs, Wc);

    cudaFuncSetAttribute(k1_proj_route, cudaFuncAttributeMaxDynamicSharedMemorySize, SMEM1);
    k1_proj_route<<<NBLK, NT1, SMEM1>>>(x, bp, out + B_SZ * C_SZ, write_idx);

    cudaFuncSetAttribute(k2_classifier, cudaFuncAttributeMaxDynamicSharedMemorySize, SMEM2);
    k2_classifier<<<K2GRID, NT2, SMEM2>>>(bc, out);
}